// round 12
// baseline (speedup 1.0000x reference)
#include <cuda_runtime.h>
#include <cuda_bf16.h>
#include <cstdint>
#include <cstddef>

// ---------------------------------------------------------------------------
// TreeLSTM: hybrid tensor+FFMA GEMM.
//   Tensor path (warps 0-7): bf16 hi/lo 3-product HMMA on 128 cols (R10).
//   FFMA path (warps 8-11, levels only): 32 extra cols in native fp32 on the
//     otherwise-idle fma pipe, A reconstructed from the same smem hi/lo
//     tiles, B from a 4KB fp32 plane added to each bulk stage. BN 128->160.
// ---------------------------------------------------------------------------

#define B_   256
#define LVS  256
#define H_   512
#define X_   300
#define NN   511
#define TH   1536
#define NC   2560
#define KLF  320            // leaf K padded to multiple of 32

#define BM   128
#define BK   32
#define OFF_AH 0
#define OFF_AL 8192
#define OFF_BH 16384
#define OFF_BL 24576
#define OFF_BF 32768

// gmem chunk-plane strides (bytes)
#define PLANE_WC  ((long)NC * 64)        // 163840
#define PLANE_WL  ((long)TH * 64)        // 98304
#define PLANE_X   ((long)B_ * LVS * 64)  // 4194304

// -------------------- static scratch ----------------------------------------
__device__ float         g_c  [(size_t)B_ * NN * H_];
__device__ float         g_buf[(size_t)B_ * LVS * TH];
__device__ __nv_bfloat16 g_hh [(size_t)B_ * NN * H_];
__device__ __nv_bfloat16 g_hl [(size_t)B_ * NN * H_];
__device__ __nv_bfloat16 g_xh [(size_t)B_ * LVS * KLF];
__device__ __nv_bfloat16 g_xl [(size_t)B_ * LVS * KLF];
__device__ __nv_bfloat16 g_wch[(size_t)NC * 1024];
__device__ __nv_bfloat16 g_wcl[(size_t)NC * 1024];
__device__ float         g_wcf[(size_t)32 * 16 * 32 * 32];   // [kc][tile][k][32cols]
__device__ __nv_bfloat16 g_wlh[(size_t)TH * KLF];
__device__ __nv_bfloat16 g_wll[(size_t)TH * KLF];
__device__ float         g_bc [NC];

// -------------------- PTX helpers -------------------------------------------
__device__ __forceinline__ uint32_t smem_u32(const void* p) {
    uint32_t a;
    asm("{ .reg .u64 t; cvta.to.shared.u64 t, %1; cvt.u32.u64 %0, t; }"
        : "=r"(a) : "l"(p));
    return a;
}
__device__ __forceinline__ void cp16(uint32_t dst, const void* src) {
    asm volatile("cp.async.cg.shared.global [%0], [%1], 16;" :: "r"(dst), "l"(src));
}
__device__ __forceinline__ void cp_commit() {
    asm volatile("cp.async.commit_group;" ::: "memory");
}
template <int N> __device__ __forceinline__ void cp_wait() {
    asm volatile("cp.async.wait_group %0;" :: "n"(N) : "memory");
}
__device__ __forceinline__ void bulk_cp(uint32_t dst, const void* src,
                                        uint32_t bytes, uint32_t mbar) {
    asm volatile(
        "cp.async.bulk.shared::cta.global.mbarrier::complete_tx::bytes "
        "[%0], [%1], %2, [%3];"
        :: "r"(dst), "l"(src), "r"(bytes), "r"(mbar) : "memory");
}
__device__ __forceinline__ void mbar_init(uint32_t a, uint32_t cnt) {
    asm volatile("mbarrier.init.shared.b64 [%0], %1;" :: "r"(a), "r"(cnt) : "memory");
}
__device__ __forceinline__ void mbar_expect(uint32_t a, uint32_t bytes) {
    asm volatile("mbarrier.arrive.expect_tx.shared.b64 _, [%0], %1;"
                 :: "r"(a), "r"(bytes) : "memory");
}
__device__ __forceinline__ void mbar_wait(uint32_t a, uint32_t parity) {
    asm volatile(
        "{\n\t.reg .pred P;\n\t"
        "W_%=:\n\t"
        "mbarrier.try_wait.parity.acquire.cta.shared::cta.b64 P, [%0], %1, 0x989680;\n\t"
        "@P bra.uni D_%=;\n\t"
        "bra.uni W_%=;\n\t"
        "D_%=:\n\t}"
        :: "r"(a), "r"(parity) : "memory");
}
__device__ __forceinline__ void fence_async() {
    asm volatile("fence.proxy.async.shared::cta;" ::: "memory");
}
__device__ __forceinline__ void ldmat4(uint32_t* r, uint32_t addr) {
    asm volatile("ldmatrix.sync.aligned.m8n8.x4.shared.b16 {%0,%1,%2,%3}, [%4];"
                 : "=r"(r[0]), "=r"(r[1]), "=r"(r[2]), "=r"(r[3]) : "r"(addr));
}
__device__ __forceinline__ void mma16816(float* c, const uint32_t* a,
                                         uint32_t b0, uint32_t b1) {
    asm volatile(
        "mma.sync.aligned.m16n8k16.row.col.f32.bf16.bf16.f32 "
        "{%0,%1,%2,%3}, {%4,%5,%6,%7}, {%8,%9}, {%0,%1,%2,%3};"
        : "+f"(c[0]), "+f"(c[1]), "+f"(c[2]), "+f"(c[3])
        : "r"(a[0]), "r"(a[1]), "r"(a[2]), "r"(a[3]), "r"(b0), "r"(b1));
}

// swizzled granule offset within a 64B row: g in 0..3, row r
__device__ __host__ __forceinline__ uint32_t swz(uint32_t g, uint32_t r) {
    return ((g + ((r >> 1) & 3)) & 3) << 4;
}

// -------------------- hybrid GEMM -------------------------------------------
// ABULK=true : A chunk-contiguous in gmem (leaf) -> bulk; NF must be 0.
// ABULK=false: A = h_cat rows via LDGSTS (levels); NF=32 FFMA columns.
// Block: 256 threads (NF=0) or 384 (NF=32). n0 = bx*(128+NF).
template <bool ABULK, int NF>
__global__ void __launch_bounds__(384, 1) gemm_hyb_kernel(
    const __nv_bfloat16* __restrict__ Ah, const __nv_bfloat16* __restrict__ Al,
    const __nv_bfloat16* __restrict__ Bh, const __nv_bfloat16* __restrict__ Bl,
    const float* __restrict__ Bf,
    const float* __restrict__ bias, float* __restrict__ C,
    int Ntot, long planeB, long planeA, int nk, int tree_lm, int off_prev)
{
    constexpr int STAGEB = 32768 + (NF > 0 ? NF * 32 * 4 : 0);
    __shared__ uint64_t mbars[2];
    extern __shared__ char smem[];
    const uint32_t sbase = smem_u32(smem);
    const uint32_t mb0 = smem_u32(&mbars[0]);
    const uint32_t mb1 = smem_u32(&mbars[1]);
    const int t = threadIdx.x;
    const int lane = t & 31, wid = t >> 5;
    const int m0 = blockIdx.y * BM;
    const int n0 = blockIdx.x * (128 + NF);

    if (t == 0) {
        mbar_init(mb0, 1);
        mbar_init(mb1, 1);
        fence_async();
    }
    __syncthreads();

    // ---------- A loader setup (levels, threads 0-255) ----------
    const char *pAh0 = nullptr, *pAh1 = nullptr, *pAl0 = nullptr, *pAl1 = nullptr;
    uint32_t dA0 = 0, dA1 = 0;
    if (!ABULK && t < 256) {
        const int row0 = t >> 2, row1 = row0 + 64;
        const int seg = t & 3;
        const int msk = (1 << tree_lm) - 1;
        const int gr0 = m0 + row0, gr1 = m0 + row1;
        const size_t a0b =
            ((size_t)(gr0 >> tree_lm) * NN + off_prev + 2 * (gr0 & msk)) * H_;
        const size_t a1b =
            ((size_t)(gr1 >> tree_lm) * NN + off_prev + 2 * (gr1 & msk)) * H_;
        pAh0 = (const char*)(Ah + a0b) + seg * 16;
        pAh1 = (const char*)(Ah + a1b) + seg * 16;
        pAl0 = (const char*)(Al + a0b) + seg * 16;
        pAl1 = (const char*)(Al + a1b) + seg * 16;
        dA0 = (uint32_t)row0 * 64 + swz(seg, row0);
        dA1 = (uint32_t)row1 * 64 + swz(seg, row1);
    }

#define LOADS(kk, st) do {                                                    \
        const uint32_t sb_ = sbase + (uint32_t)(st) * STAGEB;                 \
        if (!ABULK && t < 256) {                                              \
            const size_t gb_ = (size_t)(kk) * 64;                             \
            cp16(sb_ + OFF_AH + dA0, pAh0 + gb_);                             \
            cp16(sb_ + OFF_AH + dA1, pAh1 + gb_);                             \
            cp16(sb_ + OFF_AL + dA0, pAl0 + gb_);                             \
            cp16(sb_ + OFF_AL + dA1, pAl1 + gb_);                             \
        }                                                                     \
        cp_commit();                                                          \
        if (t == 0) {                                                         \
            mbar_expect((st) ? mb1 : mb0,                                     \
                        ABULK ? 32768u : (16384u + (NF ? NF * 128u : 0u)));   \
            const long bo_ = (long)(kk) * planeB + (long)n0 * 64;             \
            bulk_cp(sb_ + OFF_BH, (const char*)Bh + bo_, 8192, (st) ? mb1 : mb0); \
            bulk_cp(sb_ + OFF_BL, (const char*)Bl + bo_, 8192, (st) ? mb1 : mb0); \
            if (ABULK) {                                                      \
                const long ao_ = (long)(kk) * planeA + (long)m0 * 64;         \
                bulk_cp(sb_ + OFF_AH, (const char*)Ah + ao_, 8192, (st) ? mb1 : mb0); \
                bulk_cp(sb_ + OFF_AL, (const char*)Al + ao_, 8192, (st) ? mb1 : mb0); \
            }                                                                 \
            if (NF > 0) {                                                     \
                const long fo_ = (long)(kk) * ((long)gridDim.x * NF * 128)    \
                               + (long)blockIdx.x * NF * 128;                 \
                bulk_cp(sb_ + OFF_BF, (const char*)Bf + fo_, NF * 128u,       \
                        (st) ? mb1 : mb0);                                    \
            }                                                                 \
        }                                                                     \
    } while (0)

    // ---------- tensor compute setup: warps 0-7, 32x64 warp tiles ----------
    const uint32_t half = (uint32_t)(lane >> 4);
    uint32_t aRow[2], aSw[2], bRow[4], bSw[4];
    if (wid < 8) {
        const int warp_m = (wid & 3) * 32, warp_n = (wid >> 2) * 64;
#pragma unroll
        for (int mi = 0; mi < 2; mi++) {
            const uint32_t R = (uint32_t)(warp_m + mi * 16 + (lane & 15));
            aRow[mi] = R * 64;
            aSw[mi] = (R >> 1) & 3;
        }
#pragma unroll
        for (int g = 0; g < 4; g++) {
            const uint32_t R = (uint32_t)(warp_n + g * 16 + (lane & 15));
            bRow[g] = R * 64;
            bSw[g] = (R >> 1) & 3;
        }
    }

    float acc[2][8][4];
    float accf[NF > 0 ? NF : 1];
    if (wid < 8) {
#pragma unroll
        for (int mi = 0; mi < 2; mi++)
#pragma unroll
            for (int nj = 0; nj < 8; nj++)
#pragma unroll
                for (int q = 0; q < 4; q++) acc[mi][nj][q] = 0.0f;
    } else if (NF > 0) {
#pragma unroll
        for (int c = 0; c < NF; c++) accf[c] = 0.0f;
    }

    LOADS(0, 0);
    LOADS(1, 1);

    for (int k = 0; k < nk; k++) {
        if (!ABULK) {
            if (k + 1 < nk) cp_wait<1>();
            else            cp_wait<0>();
        }
        mbar_wait((k & 1) ? mb1 : mb0, (k >> 1) & 1);
        __syncthreads();

        const uint32_t sb = sbase + (uint32_t)(k & 1) * STAGEB;
        if (wid < 8) {
#pragma unroll
            for (int ks = 0; ks < 2; ks++) {
                uint32_t ah[2][4], al[2][4];
#pragma unroll
                for (int mi = 0; mi < 2; mi++) {
                    const uint32_t ad = sb + aRow[mi]
                        + ((((uint32_t)(ks << 1) + half + aSw[mi]) & 3) << 4);
                    ldmat4(ah[mi], ad + OFF_AH);
                    ldmat4(al[mi], ad + OFF_AL);
                }
#pragma unroll
                for (int g = 0; g < 4; g++) {
                    uint32_t bh[4], bl[4];
                    const uint32_t bd = sb + bRow[g]
                        + ((((uint32_t)(ks << 1) + half + bSw[g]) & 3) << 4);
                    ldmat4(bh, bd + OFF_BH);
                    ldmat4(bl, bd + OFF_BL);
#pragma unroll
                    for (int mi = 0; mi < 2; mi++) {
                        mma16816(acc[mi][2 * g],     ah[mi], bh[0], bh[2]);
                        mma16816(acc[mi][2 * g + 1], ah[mi], bh[1], bh[3]);
                    }
#pragma unroll
                    for (int mi = 0; mi < 2; mi++) {
                        mma16816(acc[mi][2 * g],     al[mi], bh[0], bh[2]);
                        mma16816(acc[mi][2 * g + 1], al[mi], bh[1], bh[3]);
                    }
#pragma unroll
                    for (int mi = 0; mi < 2; mi++) {
                        mma16816(acc[mi][2 * g],     ah[mi], bl[0], bl[2]);
                        mma16816(acc[mi][2 * g + 1], ah[mi], bl[1], bl[3]);
                    }
                }
            }
        } else if (NF > 0) {
            // ---------- FFMA path: 1 row/thread, NF fp32 cols ----------
            const uint32_t r = (uint32_t)((wid - 8) * 32 + lane);
            float a[32];
#pragma unroll
            for (int g = 0; g < 4; g++) {
                const uint32_t ro = sb + r * 64 + swz(g, r);
                uint4 h4, l4;
                asm volatile("ld.shared.v4.b32 {%0,%1,%2,%3}, [%4];"
                             : "=r"(h4.x), "=r"(h4.y), "=r"(h4.z), "=r"(h4.w)
                             : "r"(ro + OFF_AH));
                asm volatile("ld.shared.v4.b32 {%0,%1,%2,%3}, [%4];"
                             : "=r"(l4.x), "=r"(l4.y), "=r"(l4.z), "=r"(l4.w)
                             : "r"(ro + OFF_AL));
                const __nv_bfloat162* hp = (const __nv_bfloat162*)&h4;
                const __nv_bfloat162* lp = (const __nv_bfloat162*)&l4;
#pragma unroll
                for (int q = 0; q < 4; q++) {
                    const float2 fh = __bfloat1622float2(hp[q]);
                    const float2 fl = __bfloat1622float2(lp[q]);
                    a[g * 8 + 2 * q]     = fh.x + fl.x;
                    a[g * 8 + 2 * q + 1] = fh.y + fl.y;
                }
            }
            const uint32_t bfb = sb + OFF_BF;
#pragma unroll
            for (int kk2 = 0; kk2 < 32; kk2++) {
                const float av = a[kk2];
#pragma unroll
                for (int c4 = 0; c4 < NF / 4; c4++) {
                    float4 b;
                    asm volatile("ld.shared.v4.f32 {%0,%1,%2,%3}, [%4];"
                                 : "=f"(b.x), "=f"(b.y), "=f"(b.z), "=f"(b.w)
                                 : "r"(bfb + (uint32_t)(kk2 * NF + c4 * 4) * 4));
                    accf[4 * c4 + 0] += av * b.x;
                    accf[4 * c4 + 1] += av * b.y;
                    accf[4 * c4 + 2] += av * b.z;
                    accf[4 * c4 + 3] += av * b.w;
                }
            }
        }
        __syncthreads();
        if (k + 2 < nk) LOADS(k + 2, k & 1);
    }

    // ---------- epilogue ----------
    if (wid < 8) {
        const int warp_m = (wid & 3) * 32, warp_n = (wid >> 2) * 64;
        const int er = lane >> 2, ec = (lane & 3) * 2;
#pragma unroll
        for (int mi = 0; mi < 2; mi++) {
            const int rbase = m0 + warp_m + mi * 16 + er;
#pragma unroll
            for (int nj = 0; nj < 8; nj++) {
                const int col = n0 + warp_n + nj * 8 + ec;
                const float b0 = bias[col], b1 = bias[col + 1];
                float2 v;
                v.x = acc[mi][nj][0] + b0;
                v.y = acc[mi][nj][1] + b1;
                *(float2*)&C[(size_t)rbase * Ntot + col] = v;
                v.x = acc[mi][nj][2] + b0;
                v.y = acc[mi][nj][3] + b1;
                *(float2*)&C[(size_t)(rbase + 8) * Ntot + col] = v;
            }
        }
    } else if (NF > 0) {
        const int r = (wid - 8) * 32 + lane;
        float* crow = C + (size_t)(m0 + r) * Ntot + n0 + 128;
        const float* bp = bias + n0 + 128;
#pragma unroll
        for (int c4 = 0; c4 < NF / 4; c4++) {
            float4 v;
            v.x = accf[4 * c4 + 0] + bp[4 * c4 + 0];
            v.y = accf[4 * c4 + 1] + bp[4 * c4 + 1];
            v.z = accf[4 * c4 + 2] + bp[4 * c4 + 2];
            v.w = accf[4 * c4 + 3] + bp[4 * c4 + 3];
            *(float4*)(crow + 4 * c4) = v;
        }
    }
#undef LOADS
}

// -------------------- cell / epilogue kernels -------------------------------
__device__ __forceinline__ float sigf(float x) { return 1.0f / (1.0f + expf(-x)); }

__device__ __forceinline__ void store_h(size_t ob, float hn) {
    const __nv_bfloat16 hi = __float2bfloat16(hn);
    g_hh[ob] = hi;
    g_hl[ob] = __float2bfloat16(hn - __bfloat162float(hi));
}

__global__ void cell_leaf_kernel(const float* __restrict__ buf)
{
    const size_t idx = (size_t)blockIdx.x * blockDim.x + threadIdx.x;
    if (idx >= (size_t)B_ * LVS * H_) return;
    const int n = (int)(idx & (H_ - 1));
    const size_t r = idx >> 9;
    const float* row = buf + r * TH;
    const float i_ = row[n], o_ = row[n + 512], u_ = row[n + 1024];
    const float cn = sigf(i_) * tanhf(u_);
    const float hn = sigf(o_) * tanhf(cn);
    const int b = (int)(r >> 8), leaf = (int)(r & 255);
    const size_t ob = ((size_t)b * NN + leaf) * H_ + n;
    g_c[ob] = cn;
    store_h(ob, hn);
}

__global__ void cell_level_kernel(const float* __restrict__ buf,
                                  int lm, int off, int off_prev, int total)
{
    const int idx = blockIdx.x * blockDim.x + threadIdx.x;
    if (idx >= total) return;
    const int n = idx & (H_ - 1);
    const int r = idx >> 9;
    const int b = r >> lm;
    const int j = r & ((1 << lm) - 1);
    const float* row = buf + (size_t)r * NC;
    const float i_ = row[n], o_ = row[n + 512], u_ = row[n + 1024];
    const float f0 = row[1536 + n], f1 = row[2048 + n];
    const size_t cb = ((size_t)b * NN + off_prev + 2 * j) * H_ + n;
    const float cf = sigf(f0) * g_c[cb] + sigf(f1) * g_c[cb + H_];
    const float cn = sigf(i_) * tanhf(u_) + cf;
    const float hn = sigf(o_) * tanhf(cn);
    const size_t ob = ((size_t)b * NN + off + j) * H_ + n;
    g_c[ob] = cn;
    store_h(ob, hn);
}

__global__ void classify_kernel(const float* __restrict__ lw,
                                const float* __restrict__ lb,
                                float* __restrict__ out)
{
    const int node = blockIdx.x * blockDim.x + threadIdx.x;
    if (node >= B_ * NN) return;
    const __nv_bfloat162* hh = (const __nv_bfloat162*)(g_hh + (size_t)node * H_);
    const __nv_bfloat162* hl = (const __nv_bfloat162*)(g_hl + (size_t)node * H_);
    float acc[5] = {0.f, 0.f, 0.f, 0.f, 0.f};
#pragma unroll 4
    for (int k2 = 0; k2 < 256; k2++) {
        const float2 a = __bfloat1622float2(hh[k2]);
        const float2 b = __bfloat1622float2(hl[k2]);
        const float h0 = a.x + b.x, h1 = a.y + b.y;
#pragma unroll
        for (int c = 0; c < 5; c++)
            acc[c] += h0 * lw[c * H_ + 2 * k2] + h1 * lw[c * H_ + 2 * k2 + 1];
    }
#pragma unroll
    for (int c = 0; c < 5; c++)
        out[(size_t)node * 5 + c] = acc[c] + lb[c];
}

// -------------------- packing / gather (chunked + swizzled) -----------------
__device__ __forceinline__ void split_store(float v, __nv_bfloat16* hi,
                                            __nv_bfloat16* lo, size_t half_idx) {
    const __nv_bfloat16 h = __float2bfloat16(v);
    hi[half_idx] = h;
    lo[half_idx] = __float2bfloat16(v - __bfloat162float(h));
}
__device__ __forceinline__ size_t chunk_off(int row, int k, long plane) {
    const int kc = k >> 5;
    const uint32_t g = ((uint32_t)(k & 31)) >> 3;
    const size_t byte = (size_t)kc * plane + (size_t)row * 64
                      + swz(g, (uint32_t)row) + (size_t)(k & 7) * 2;
    return byte >> 1;   // bf16 index
}

__global__ void pack_wcat_kernel(const float* __restrict__ Uiou,
                                 const float* __restrict__ Uf)
{
    const int idx = blockIdx.x * blockDim.x + threadIdx.x;
    if (idx >= NC * 1024) return;
    const int n = idx >> 10, k = idx & 1023;
    const float v = (n < TH) ? Uiou[(size_t)n * 1024 + k]
                             : Uf[(size_t)(n - TH) * 1024 + k];
    split_store(v, g_wch, g_wcl, chunk_off(n, k, PLANE_WC));
    const int tile = n / 160, c = n - tile * 160;
    if (c >= 128) {
        const size_t fi = (((size_t)(k >> 5) * 16 + tile) * 32 + (k & 31)) * 32
                        + (c - 128);
        g_wcf[fi] = v;
    }
}

__global__ void pack_wleaf_kernel(const float* __restrict__ W)
{
    const int idx = blockIdx.x * blockDim.x + threadIdx.x;
    if (idx >= TH * KLF) return;
    const int n = idx / KLF, k = idx - n * KLF;
    const float v = (k < X_) ? W[(size_t)n * X_ + k] : 0.0f;
    split_store(v, g_wlh, g_wll, chunk_off(n, k, PLANE_WL));
}

__global__ void pack_bias_kernel(const float* __restrict__ bi,
                                 const float* __restrict__ bf)
{
    const int n = blockIdx.x * blockDim.x + threadIdx.x;
    if (n < NC) g_bc[n] = (n < TH) ? bi[n] : bf[n - TH];
}

__global__ void gather_x_kernel(const int* __restrict__ wid,
                                const float* __restrict__ emb)
{
    const int r = blockIdx.x;
    const int c = threadIdx.x;
    if (c >= KLF) return;
    const float v = (c < X_) ? emb[(size_t)wid[r] * X_ + c] : 0.0f;
    split_store(v, g_xh, g_xl, chunk_off(r, c, PLANE_X));
}

// -------------------- launch ------------------------------------------------
extern "C" void kernel_launch(void* const* d_in, const int* in_sizes, int n_in,
                              void* d_out, int out_size)
{
    const int*   wordid  = (const int*)  d_in[0];
    const float* emb     = (const float*)d_in[1];
    const float* W_iou_w = (const float*)d_in[2];
    const float* W_iou_b = (const float*)d_in[3];
    const float* U_iou_w = (const float*)d_in[4];
    const float* U_iou_b = (const float*)d_in[5];
    const float* U_f_w   = (const float*)d_in[6];
    const float* U_f_b   = (const float*)d_in[7];
    const float* lin_w   = (const float*)d_in[8];
    const float* lin_b   = (const float*)d_in[9];
    float* out = (float*)d_out;
    (void)in_sizes; (void)n_in; (void)out_size;

    float *pbuf, *pbc, *pwcf;
    __nv_bfloat16 *phh, *phl, *pxh, *pxl, *pwch, *pwcl, *pwlh, *pwll;
    cudaGetSymbolAddress((void**)&pbuf, g_buf);
    cudaGetSymbolAddress((void**)&pbc,  g_bc);
    cudaGetSymbolAddress((void**)&pwcf, g_wcf);
    cudaGetSymbolAddress((void**)&phh,  g_hh);
    cudaGetSymbolAddress((void**)&phl,  g_hl);
    cudaGetSymbolAddress((void**)&pxh,  g_xh);
    cudaGetSymbolAddress((void**)&pxl,  g_xl);
    cudaGetSymbolAddress((void**)&pwch, g_wch);
    cudaGetSymbolAddress((void**)&pwcl, g_wcl);
    cudaGetSymbolAddress((void**)&pwlh, g_wlh);
    cudaGetSymbolAddress((void**)&pwll, g_wll);

    const int smemLeaf = 2 * 32768;                 // 65536
    const int smemLvl  = 2 * (32768 + 32 * 32 * 4); // 73728
    cudaFuncSetAttribute(gemm_hyb_kernel<true, 0>,
                         cudaFuncAttributeMaxDynamicSharedMemorySize, smemLeaf);
    cudaFuncSetAttribute(gemm_hyb_kernel<false, 32>,
                         cudaFuncAttributeMaxDynamicSharedMemorySize, smemLvl);

    // ---- prep ----
    pack_wcat_kernel <<<(NC * 1024 + 255) / 256, 256>>>(U_iou_w, U_f_w);
    pack_wleaf_kernel<<<(TH * KLF + 255) / 256, 256>>>(W_iou_w);
    pack_bias_kernel <<<(NC + 255) / 256, 256>>>(U_iou_b, U_f_b);
    gather_x_kernel  <<<B_ * LVS, KLF>>>(wordid, emb);

    // ---- leaves: all-bulk tensor GEMM (BN=128) ----
    {
        dim3 g(TH / 128, (B_ * LVS) / BM);   // 12 x 512
        gemm_hyb_kernel<true, 0><<<g, 256, smemLeaf>>>(
            pxh, pxl, pwlh, pwll, nullptr, W_iou_b, pbuf,
            TH, PLANE_WL, PLANE_X, KLF / BK, 0, 0);
        cell_leaf_kernel<<<(B_ * LVS * H_) / 256, 256>>>(pbuf);
    }

    // ---- internal levels: hybrid GEMM (BN=160 = 128 tensor + 32 FFMA) ----
    static const int offs[10] = {0, 256, 384, 448, 480, 496, 504, 508, 510, 511};
    for (int l = 1; l <= 8; l++) {
        const int m = LVS >> l;
        const int M = B_ * m;
        const int lm = 8 - l;
        dim3 g(NC / 160, M / BM);            // 16 x (M/128)
        gemm_hyb_kernel<false, 32><<<g, 384, smemLvl>>>(
            phh, phl, pwch, pwcl, pwcf, pbc, pbuf,
            NC, PLANE_WC, 0, 1024 / BK, lm, offs[l - 1]);
        const int total = M * H_;
        cell_level_kernel<<<(total + 255) / 256, 256>>>(pbuf, lm, offs[l],
                                                        offs[l - 1], total);
    }

    // ---- classifier ----
    classify_kernel<<<(B_ * NN + 127) / 128, 128>>>(lin_w, lin_b, out);
}

// round 13
// speedup vs baseline: 1.3335x; 1.3335x over previous
#include <cuda_runtime.h>
#include <cuda_bf16.h>
#include <cstdint>
#include <cstddef>

// ---------------------------------------------------------------------------
// TreeLSTM via mma.sync (HMMA) bf16 GEMM, hi/lo split compensation:
//   C = Ahi*Bhi + Alo*Bhi + Ahi*Blo   (fp32 register accumulation)
// R13 = R10 (best, 4425us) + split-K (S=4, gridDim.z) for deep levels 5-8 to
//   recover ~140us of wave-quantization idle time. Partials land in disjoint
//   g_buf slices (bias only on split 0); cell_level sums them.
// ---------------------------------------------------------------------------

#define B_   256
#define LVS  256
#define H_   512
#define X_   300
#define NN   511
#define TH   1536
#define NC   2560
#define KLF  320            // leaf K padded to multiple of 32

#define BM   128
#define BN   128
#define BK   32
// per-stage smem: 4 planes of 8KB (Ah, Al, Bh, Bl), 64B rows, swizzled
#define OFF_AH 0
#define OFF_AL 8192
#define OFF_BH 16384
#define OFF_BL 24576
#define STAGE  32768
#define SMEM_BYTES (2 * STAGE)   // 65536 -> 2 CTAs/SM

// gmem chunk-plane strides (bytes)
#define PLANE_WC  ((long)NC * 64)        // 163840
#define PLANE_WL  ((long)TH * 64)        // 98304
#define PLANE_X   ((long)B_ * LVS * 64)  // 4194304

// -------------------- static scratch ----------------------------------------
__device__ float         g_c  [(size_t)B_ * NN * H_];
__device__ float         g_buf[(size_t)B_ * LVS * TH];
__device__ __nv_bfloat16 g_hh [(size_t)B_ * NN * H_];
__device__ __nv_bfloat16 g_hl [(size_t)B_ * NN * H_];
__device__ __nv_bfloat16 g_xh [(size_t)B_ * LVS * KLF];   // chunked+swizzled
__device__ __nv_bfloat16 g_xl [(size_t)B_ * LVS * KLF];
__device__ __nv_bfloat16 g_wch[(size_t)NC * 1024];        // chunked+swizzled
__device__ __nv_bfloat16 g_wcl[(size_t)NC * 1024];
__device__ __nv_bfloat16 g_wlh[(size_t)TH * KLF];         // chunked+swizzled
__device__ __nv_bfloat16 g_wll[(size_t)TH * KLF];
__device__ float         g_bc [NC];

// -------------------- PTX helpers -------------------------------------------
__device__ __forceinline__ uint32_t smem_u32(const void* p) {
    uint32_t a;
    asm("{ .reg .u64 t; cvta.to.shared.u64 t, %1; cvt.u32.u64 %0, t; }"
        : "=r"(a) : "l"(p));
    return a;
}
__device__ __forceinline__ void cp16(uint32_t dst, const void* src) {
    asm volatile("cp.async.cg.shared.global [%0], [%1], 16;" :: "r"(dst), "l"(src));
}
__device__ __forceinline__ void cp_commit() {
    asm volatile("cp.async.commit_group;" ::: "memory");
}
template <int N> __device__ __forceinline__ void cp_wait() {
    asm volatile("cp.async.wait_group %0;" :: "n"(N) : "memory");
}
__device__ __forceinline__ void bulk_cp(uint32_t dst, const void* src,
                                        uint32_t bytes, uint32_t mbar) {
    asm volatile(
        "cp.async.bulk.shared::cta.global.mbarrier::complete_tx::bytes "
        "[%0], [%1], %2, [%3];"
        :: "r"(dst), "l"(src), "r"(bytes), "r"(mbar) : "memory");
}
__device__ __forceinline__ void mbar_init(uint32_t a, uint32_t cnt) {
    asm volatile("mbarrier.init.shared.b64 [%0], %1;" :: "r"(a), "r"(cnt) : "memory");
}
__device__ __forceinline__ void mbar_expect(uint32_t a, uint32_t bytes) {
    asm volatile("mbarrier.arrive.expect_tx.shared.b64 _, [%0], %1;"
                 :: "r"(a), "r"(bytes) : "memory");
}
__device__ __forceinline__ void mbar_wait(uint32_t a, uint32_t parity) {
    asm volatile(
        "{\n\t.reg .pred P;\n\t"
        "W_%=:\n\t"
        "mbarrier.try_wait.parity.acquire.cta.shared::cta.b64 P, [%0], %1, 0x989680;\n\t"
        "@P bra.uni D_%=;\n\t"
        "bra.uni W_%=;\n\t"
        "D_%=:\n\t}"
        :: "r"(a), "r"(parity) : "memory");
}
__device__ __forceinline__ void fence_async() {
    asm volatile("fence.proxy.async.shared::cta;" ::: "memory");
}
__device__ __forceinline__ void ldmat4(uint32_t* r, uint32_t addr) {
    asm volatile("ldmatrix.sync.aligned.m8n8.x4.shared.b16 {%0,%1,%2,%3}, [%4];"
                 : "=r"(r[0]), "=r"(r[1]), "=r"(r[2]), "=r"(r[3]) : "r"(addr));
}
__device__ __forceinline__ void mma16816(float* c, const uint32_t* a,
                                         uint32_t b0, uint32_t b1) {
    asm volatile(
        "mma.sync.aligned.m16n8k16.row.col.f32.bf16.bf16.f32 "
        "{%0,%1,%2,%3}, {%4,%5,%6,%7}, {%8,%9}, {%0,%1,%2,%3};"
        : "+f"(c[0]), "+f"(c[1]), "+f"(c[2]), "+f"(c[3])
        : "r"(a[0]), "r"(a[1]), "r"(a[2]), "r"(a[3]), "r"(b0), "r"(b1));
}

// swizzled granule offset within a 64B row: g in 0..3, row r
__device__ __host__ __forceinline__ uint32_t swz(uint32_t g, uint32_t r) {
    return ((g + ((r >> 1) & 3)) & 3) << 4;
}

// -------------------- HMMA GEMM ---------------------------------------------
// ABULK=true : A chunk-contiguous in gmem (leaf) -> bulk copies.
// ABULK=false: A = h_cat rows (tree mapping), loaded via LDGSTS.
// Split-K: blockIdx.z = split index; kof = z*nk chunks; output goes to
//   C + z*splitE; bias added only by split 0.
template <bool ABULK>
__global__ void __launch_bounds__(256, 2) gemm_mma_kernel(
    const __nv_bfloat16* __restrict__ Ah, const __nv_bfloat16* __restrict__ Al,
    const __nv_bfloat16* __restrict__ Bh, const __nv_bfloat16* __restrict__ Bl,
    const float* __restrict__ bias, float* __restrict__ C,
    int Ntot, long planeB, long planeA, int nk, int tree_lm, int off_prev,
    size_t splitE)
{
    __shared__ uint64_t mbars[2];
    extern __shared__ char smem[];
    const uint32_t sbase = smem_u32(smem);
    const uint32_t mb0 = smem_u32(&mbars[0]);
    const uint32_t mb1 = smem_u32(&mbars[1]);
    const int t = threadIdx.x;
    const int lane = t & 31, wid = t >> 5;
    const int m0 = blockIdx.y * BM, n0 = blockIdx.x * BN;
    const int kof = blockIdx.z * nk;
    C += (size_t)blockIdx.z * splitE;
    const float bscale = (blockIdx.z == 0) ? 1.0f : 0.0f;

    if (t == 0) {
        mbar_init(mb0, 1);
        mbar_init(mb1, 1);
        fence_async();
    }
    __syncthreads();

    // ---------- A loader setup (levels only): rows t>>2 and +64, seg t&3 ----
    const char *pAh0 = nullptr, *pAh1 = nullptr, *pAl0 = nullptr, *pAl1 = nullptr;
    uint32_t dA0 = 0, dA1 = 0;
    if (!ABULK) {
        const int row0 = t >> 2, row1 = row0 + 64;
        const int seg = t & 3;
        const int msk = (1 << tree_lm) - 1;
        const int gr0 = m0 + row0, gr1 = m0 + row1;
        const size_t a0b =
            ((size_t)(gr0 >> tree_lm) * NN + off_prev + 2 * (gr0 & msk)) * H_;
        const size_t a1b =
            ((size_t)(gr1 >> tree_lm) * NN + off_prev + 2 * (gr1 & msk)) * H_;
        pAh0 = (const char*)(Ah + a0b) + seg * 16;
        pAh1 = (const char*)(Ah + a1b) + seg * 16;
        pAl0 = (const char*)(Al + a0b) + seg * 16;
        pAl1 = (const char*)(Al + a1b) + seg * 16;
        dA0 = (uint32_t)row0 * 64 + swz(seg, row0);
        dA1 = (uint32_t)row1 * 64 + swz(seg, row1);
    }

#define LOADS(kk, st) do {                                                    \
        const uint32_t sb_ = sbase + (uint32_t)(st) * STAGE;                  \
        const uint32_t mbar_ = (st) ? mb1 : mb0;                              \
        const int kg_ = kof + (kk);                                           \
        if (!ABULK) {                                                         \
            const size_t gb_ = (size_t)kg_ * 64;                              \
            cp16(sb_ + OFF_AH + dA0, pAh0 + gb_);                             \
            cp16(sb_ + OFF_AH + dA1, pAh1 + gb_);                             \
            cp16(sb_ + OFF_AL + dA0, pAl0 + gb_);                             \
            cp16(sb_ + OFF_AL + dA1, pAl1 + gb_);                             \
            cp_commit();                                                      \
        }                                                                     \
        if (t == 0) {                                                         \
            mbar_expect(mbar_, ABULK ? 32768u : 16384u);                      \
            const long bo_ = (long)kg_ * planeB + (long)n0 * 64;              \
            bulk_cp(sb_ + OFF_BH, (const char*)Bh + bo_, 8192, mbar_);        \
            bulk_cp(sb_ + OFF_BL, (const char*)Bl + bo_, 8192, mbar_);        \
            if (ABULK) {                                                      \
                const long ao_ = (long)kg_ * planeA + (long)m0 * 64;          \
                bulk_cp(sb_ + OFF_AH, (const char*)Ah + ao_, 8192, mbar_);    \
                bulk_cp(sb_ + OFF_AL, (const char*)Al + ao_, 8192, mbar_);    \
            }                                                                 \
        }                                                                     \
    } while (0)

    // ---------- compute setup: 4x2 warp grid, 32x64 warp tile ----------
    const int warp_m = (wid & 3) * 32, warp_n = (wid >> 2) * 64;
    const uint32_t half = (uint32_t)(lane >> 4);
    uint32_t aRow[2], aSw[2], bRow[4], bSw[4];
#pragma unroll
    for (int mi = 0; mi < 2; mi++) {
        const uint32_t R = (uint32_t)(warp_m + mi * 16 + (lane & 15));
        aRow[mi] = R * 64;
        aSw[mi] = (R >> 1) & 3;
    }
#pragma unroll
    for (int g = 0; g < 4; g++) {
        const uint32_t R = (uint32_t)(warp_n + g * 16 + (lane & 15));
        bRow[g] = R * 64;
        bSw[g] = (R >> 1) & 3;
    }

    float acc[2][8][4];
#pragma unroll
    for (int mi = 0; mi < 2; mi++)
#pragma unroll
        for (int nj = 0; nj < 8; nj++)
#pragma unroll
            for (int q = 0; q < 4; q++) acc[mi][nj][q] = 0.0f;

    LOADS(0, 0);
    LOADS(1, 1);

    for (int k = 0; k < nk; k++) {
        if (!ABULK) {
            if (k + 1 < nk) cp_wait<1>();
            else            cp_wait<0>();
        }
        mbar_wait((k & 1) ? mb1 : mb0, (k >> 1) & 1);
        __syncthreads();

        const uint32_t sb = sbase + (uint32_t)(k & 1) * STAGE;
#pragma unroll
        for (int ks = 0; ks < 2; ks++) {
            uint32_t ah[2][4], al[2][4];
#pragma unroll
            for (int mi = 0; mi < 2; mi++) {
                const uint32_t ad = sb + aRow[mi]
                    + ((((uint32_t)(ks << 1) + half + aSw[mi]) & 3) << 4);
                ldmat4(ah[mi], ad + OFF_AH);
                ldmat4(al[mi], ad + OFF_AL);
            }
#pragma unroll
            for (int g = 0; g < 4; g++) {
                uint32_t bh[4], bl[4];
                const uint32_t bd = sb + bRow[g]
                    + ((((uint32_t)(ks << 1) + half + bSw[g]) & 3) << 4);
                ldmat4(bh, bd + OFF_BH);
                ldmat4(bl, bd + OFF_BL);
#pragma unroll
                for (int mi = 0; mi < 2; mi++) {
                    mma16816(acc[mi][2 * g],     ah[mi], bh[0], bh[2]);
                    mma16816(acc[mi][2 * g + 1], ah[mi], bh[1], bh[3]);
                }
#pragma unroll
                for (int mi = 0; mi < 2; mi++) {
                    mma16816(acc[mi][2 * g],     al[mi], bh[0], bh[2]);
                    mma16816(acc[mi][2 * g + 1], al[mi], bh[1], bh[3]);
                }
#pragma unroll
                for (int mi = 0; mi < 2; mi++) {
                    mma16816(acc[mi][2 * g],     ah[mi], bl[0], bl[2]);
                    mma16816(acc[mi][2 * g + 1], ah[mi], bl[1], bl[3]);
                }
            }
        }
        __syncthreads();
        if (k + 2 < nk) LOADS(k + 2, k & 1);
    }

    // ---------- epilogue ----------
    const int er = lane >> 2, ec = (lane & 3) * 2;
#pragma unroll
    for (int mi = 0; mi < 2; mi++) {
        const int rbase = m0 + warp_m + mi * 16 + er;
#pragma unroll
        for (int nj = 0; nj < 8; nj++) {
            const int col = n0 + warp_n + nj * 8 + ec;
            const float b0 = bias[col] * bscale, b1 = bias[col + 1] * bscale;
            float2 v;
            v.x = acc[mi][nj][0] + b0;
            v.y = acc[mi][nj][1] + b1;
            *(float2*)&C[(size_t)rbase * Ntot + col] = v;
            v.x = acc[mi][nj][2] + b0;
            v.y = acc[mi][nj][3] + b1;
            *(float2*)&C[(size_t)(rbase + 8) * Ntot + col] = v;
        }
    }
#undef LOADS
}

// -------------------- cell / epilogue kernels -------------------------------
__device__ __forceinline__ float sigf(float x) { return 1.0f / (1.0f + expf(-x)); }

__device__ __forceinline__ void store_h(size_t ob, float hn) {
    const __nv_bfloat16 hi = __float2bfloat16(hn);
    g_hh[ob] = hi;
    g_hl[ob] = __float2bfloat16(hn - __bfloat162float(hi));
}

__global__ void cell_leaf_kernel(const float* __restrict__ buf)
{
    const size_t idx = (size_t)blockIdx.x * blockDim.x + threadIdx.x;
    if (idx >= (size_t)B_ * LVS * H_) return;
    const int n = (int)(idx & (H_ - 1));
    const size_t r = idx >> 9;
    const float* row = buf + r * TH;
    const float i_ = row[n], o_ = row[n + 512], u_ = row[n + 1024];
    const float cn = sigf(i_) * tanhf(u_);
    const float hn = sigf(o_) * tanhf(cn);
    const int b = (int)(r >> 8), leaf = (int)(r & 255);
    const size_t ob = ((size_t)b * NN + leaf) * H_ + n;
    g_c[ob] = cn;
    store_h(ob, hn);
}

// nsplit partial buffers at stride splitE; split 0 already contains bias.
__global__ void cell_level_kernel(const float* __restrict__ buf,
                                  int lm, int off, int off_prev, int total,
                                  int nsplit, size_t splitE)
{
    const int idx = blockIdx.x * blockDim.x + threadIdx.x;
    if (idx >= total) return;
    const int n = idx & (H_ - 1);
    const int r = idx >> 9;
    const int b = r >> lm;
    const int j = r & ((1 << lm) - 1);
    const size_t base = (size_t)r * NC;
    float i_ = buf[base + n];
    float o_ = buf[base + n + 512];
    float u_ = buf[base + n + 1024];
    float f0 = buf[base + n + 1536];
    float f1 = buf[base + n + 2048];
    for (int s = 1; s < nsplit; s++) {
        const size_t sb = base + (size_t)s * splitE;
        i_ += buf[sb + n];
        o_ += buf[sb + n + 512];
        u_ += buf[sb + n + 1024];
        f0 += buf[sb + n + 1536];
        f1 += buf[sb + n + 2048];
    }
    const size_t cb = ((size_t)b * NN + off_prev + 2 * j) * H_ + n;
    const float cf = sigf(f0) * g_c[cb] + sigf(f1) * g_c[cb + H_];
    const float cn = sigf(i_) * tanhf(u_) + cf;
    const float hn = sigf(o_) * tanhf(cn);
    const size_t ob = ((size_t)b * NN + off + j) * H_ + n;
    g_c[ob] = cn;
    store_h(ob, hn);
}

__global__ void classify_kernel(const float* __restrict__ lw,
                                const float* __restrict__ lb,
                                float* __restrict__ out)
{
    const int node = blockIdx.x * blockDim.x + threadIdx.x;
    if (node >= B_ * NN) return;
    const __nv_bfloat162* hh = (const __nv_bfloat162*)(g_hh + (size_t)node * H_);
    const __nv_bfloat162* hl = (const __nv_bfloat162*)(g_hl + (size_t)node * H_);
    float acc[5] = {0.f, 0.f, 0.f, 0.f, 0.f};
#pragma unroll 4
    for (int k2 = 0; k2 < 256; k2++) {
        const float2 a = __bfloat1622float2(hh[k2]);
        const float2 b = __bfloat1622float2(hl[k2]);
        const float h0 = a.x + b.x, h1 = a.y + b.y;
#pragma unroll
        for (int c = 0; c < 5; c++)
            acc[c] += h0 * lw[c * H_ + 2 * k2] + h1 * lw[c * H_ + 2 * k2 + 1];
    }
#pragma unroll
    for (int c = 0; c < 5; c++)
        out[(size_t)node * 5 + c] = acc[c] + lb[c];
}

// -------------------- packing / gather (chunked + swizzled) -----------------
__device__ __forceinline__ void split_store(float v, __nv_bfloat16* hi,
                                            __nv_bfloat16* lo, size_t half_idx) {
    const __nv_bfloat16 h = __float2bfloat16(v);
    hi[half_idx] = h;
    lo[half_idx] = __float2bfloat16(v - __bfloat162float(h));
}
__device__ __forceinline__ size_t chunk_off(int row, int k, long plane) {
    const int kc = k >> 5;
    const uint32_t g = ((uint32_t)(k & 31)) >> 3;
    const size_t byte = (size_t)kc * plane + (size_t)row * 64
                      + swz(g, (uint32_t)row) + (size_t)(k & 7) * 2;
    return byte >> 1;   // bf16 index
}

__global__ void pack_wcat_kernel(const float* __restrict__ Uiou,
                                 const float* __restrict__ Uf)
{
    const int idx = blockIdx.x * blockDim.x + threadIdx.x;
    if (idx >= NC * 1024) return;
    const int n = idx >> 10, k = idx & 1023;
    const float v = (n < TH) ? Uiou[(size_t)n * 1024 + k]
                             : Uf[(size_t)(n - TH) * 1024 + k];
    split_store(v, g_wch, g_wcl, chunk_off(n, k, PLANE_WC));
}

__global__ void pack_wleaf_kernel(const float* __restrict__ W)
{
    const int idx = blockIdx.x * blockDim.x + threadIdx.x;
    if (idx >= TH * KLF) return;
    const int n = idx / KLF, k = idx - n * KLF;
    const float v = (k < X_) ? W[(size_t)n * X_ + k] : 0.0f;
    split_store(v, g_wlh, g_wll, chunk_off(n, k, PLANE_WL));
}

__global__ void pack_bias_kernel(const float* __restrict__ bi,
                                 const float* __restrict__ bf)
{
    const int n = blockIdx.x * blockDim.x + threadIdx.x;
    if (n < NC) g_bc[n] = (n < TH) ? bi[n] : bf[n - TH];
}

__global__ void gather_x_kernel(const int* __restrict__ wid,
                                const float* __restrict__ emb)
{
    const int r = blockIdx.x;
    const int c = threadIdx.x;
    if (c >= KLF) return;
    const float v = (c < X_) ? emb[(size_t)wid[r] * X_ + c] : 0.0f;
    split_store(v, g_xh, g_xl, chunk_off(r, c, PLANE_X));
}

// -------------------- launch ------------------------------------------------
extern "C" void kernel_launch(void* const* d_in, const int* in_sizes, int n_in,
                              void* d_out, int out_size)
{
    const int*   wordid  = (const int*)  d_in[0];
    const float* emb     = (const float*)d_in[1];
    const float* W_iou_w = (const float*)d_in[2];
    const float* W_iou_b = (const float*)d_in[3];
    const float* U_iou_w = (const float*)d_in[4];
    const float* U_iou_b = (const float*)d_in[5];
    const float* U_f_w   = (const float*)d_in[6];
    const float* U_f_b   = (const float*)d_in[7];
    const float* lin_w   = (const float*)d_in[8];
    const float* lin_b   = (const float*)d_in[9];
    float* out = (float*)d_out;
    (void)in_sizes; (void)n_in; (void)out_size;

    float *pbuf, *pbc;
    __nv_bfloat16 *phh, *phl, *pxh, *pxl, *pwch, *pwcl, *pwlh, *pwll;
    cudaGetSymbolAddress((void**)&pbuf, g_buf);
    cudaGetSymbolAddress((void**)&pbc,  g_bc);
    cudaGetSymbolAddress((void**)&phh,  g_hh);
    cudaGetSymbolAddress((void**)&phl,  g_hl);
    cudaGetSymbolAddress((void**)&pxh,  g_xh);
    cudaGetSymbolAddress((void**)&pxl,  g_xl);
    cudaGetSymbolAddress((void**)&pwch, g_wch);
    cudaGetSymbolAddress((void**)&pwcl, g_wcl);
    cudaGetSymbolAddress((void**)&pwlh, g_wlh);
    cudaGetSymbolAddress((void**)&pwll, g_wll);

    cudaFuncSetAttribute(gemm_mma_kernel<false>,
                         cudaFuncAttributeMaxDynamicSharedMemorySize, SMEM_BYTES);
    cudaFuncSetAttribute(gemm_mma_kernel<true>,
                         cudaFuncAttributeMaxDynamicSharedMemorySize, SMEM_BYTES);

    // ---- prep ----
    pack_wcat_kernel <<<(NC * 1024 + 255) / 256, 256>>>(U_iou_w, U_f_w);
    pack_wleaf_kernel<<<(TH * KLF + 255) / 256, 256>>>(W_iou_w);
    pack_bias_kernel <<<(NC + 255) / 256, 256>>>(U_iou_b, U_f_b);
    gather_x_kernel  <<<B_ * LVS, KLF>>>(wordid, emb);

    // ---- leaves: all-bulk GEMM ----
    {
        dim3 g(TH / BN, (B_ * LVS) / BM, 1);   // 12 x 512
        gemm_mma_kernel<true><<<g, 256, SMEM_BYTES>>>(
            pxh, pxl, pwlh, pwll, W_iou_b, pbuf,
            TH, PLANE_WL, PLANE_X, KLF / BK, 0, 0, 0);
        cell_leaf_kernel<<<(B_ * LVS * H_) / 256, 256>>>(pbuf);
    }

    // ---- internal levels: bulk-B, LDGSTS-A GEMM; split-K for deep levels ---
    static const int offs[10] = {0, 256, 384, 448, 480, 496, 504, 508, 510, 511};
    for (int l = 1; l <= 8; l++) {
        const int m = LVS >> l;
        const int M = B_ * m;
        const int lm = 8 - l;
        const int S = (l >= 5) ? 4 : 1;        // split-K for small grids
        const size_t splitE = (size_t)M * NC;
        dim3 g(NC / BN, M / BM, S);
        gemm_mma_kernel<false><<<g, 256, SMEM_BYTES>>>(
            phh, phl, pwch, pwcl, pbc, pbuf,
            NC, PLANE_WC, 0, (1024 / BK) / S, lm, offs[l - 1], splitE);
        const int total = M * H_;
        cell_level_kernel<<<(total + 255) / 256, 256>>>(pbuf, lm, offs[l],
                                                        offs[l - 1], total,
                                                        S, splitE);
    }

    // ---- classifier ----
    classify_kernel<<<(B_ * NN + 127) / 128, 128>>>(lin_w, lin_b, out);
}

// round 14
// speedup vs baseline: 1.4102x; 1.0576x over previous
#include <cuda_runtime.h>
#include <cuda_bf16.h>
#include <cstdint>
#include <cstddef>

// ---------------------------------------------------------------------------
// TreeLSTM via mma.sync (HMMA) bf16 GEMM, hi/lo split compensation:
//   C = Ahi*Bhi + Alo*Bhi + Ahi*Blo   (fp32 register accumulation)
// R14 = R13 (best, 4308us) +
//   * warp-per-node classifier (coalesced h reads; was 8x sector-amplified)
//   * tuned split-K: S = {l4:2, l5:4, l6:4, l7:8, l8:8}
//   * bias packing fused into pack_wcat
// ---------------------------------------------------------------------------

#define B_   256
#define LVS  256
#define H_   512
#define X_   300
#define NN   511
#define TH   1536
#define NC   2560
#define KLF  320            // leaf K padded to multiple of 32

#define BM   128
#define BN   128
#define BK   32
// per-stage smem: 4 planes of 8KB (Ah, Al, Bh, Bl), 64B rows, swizzled
#define OFF_AH 0
#define OFF_AL 8192
#define OFF_BH 16384
#define OFF_BL 24576
#define STAGE  32768
#define SMEM_BYTES (2 * STAGE)   // 65536 -> 2 CTAs/SM

// gmem chunk-plane strides (bytes)
#define PLANE_WC  ((long)NC * 64)        // 163840
#define PLANE_WL  ((long)TH * 64)        // 98304
#define PLANE_X   ((long)B_ * LVS * 64)  // 4194304

// -------------------- static scratch ----------------------------------------
__device__ float         g_c  [(size_t)B_ * NN * H_];
__device__ float         g_buf[(size_t)B_ * LVS * TH];
__device__ __nv_bfloat16 g_hh [(size_t)B_ * NN * H_];
__device__ __nv_bfloat16 g_hl [(size_t)B_ * NN * H_];
__device__ __nv_bfloat16 g_xh [(size_t)B_ * LVS * KLF];   // chunked+swizzled
__device__ __nv_bfloat16 g_xl [(size_t)B_ * LVS * KLF];
__device__ __nv_bfloat16 g_wch[(size_t)NC * 1024];        // chunked+swizzled
__device__ __nv_bfloat16 g_wcl[(size_t)NC * 1024];
__device__ __nv_bfloat16 g_wlh[(size_t)TH * KLF];         // chunked+swizzled
__device__ __nv_bfloat16 g_wll[(size_t)TH * KLF];
__device__ float         g_bc [NC];

// -------------------- PTX helpers -------------------------------------------
__device__ __forceinline__ uint32_t smem_u32(const void* p) {
    uint32_t a;
    asm("{ .reg .u64 t; cvta.to.shared.u64 t, %1; cvt.u32.u64 %0, t; }"
        : "=r"(a) : "l"(p));
    return a;
}
__device__ __forceinline__ void cp16(uint32_t dst, const void* src) {
    asm volatile("cp.async.cg.shared.global [%0], [%1], 16;" :: "r"(dst), "l"(src));
}
__device__ __forceinline__ void cp_commit() {
    asm volatile("cp.async.commit_group;" ::: "memory");
}
template <int N> __device__ __forceinline__ void cp_wait() {
    asm volatile("cp.async.wait_group %0;" :: "n"(N) : "memory");
}
__device__ __forceinline__ void bulk_cp(uint32_t dst, const void* src,
                                        uint32_t bytes, uint32_t mbar) {
    asm volatile(
        "cp.async.bulk.shared::cta.global.mbarrier::complete_tx::bytes "
        "[%0], [%1], %2, [%3];"
        :: "r"(dst), "l"(src), "r"(bytes), "r"(mbar) : "memory");
}
__device__ __forceinline__ void mbar_init(uint32_t a, uint32_t cnt) {
    asm volatile("mbarrier.init.shared.b64 [%0], %1;" :: "r"(a), "r"(cnt) : "memory");
}
__device__ __forceinline__ void mbar_expect(uint32_t a, uint32_t bytes) {
    asm volatile("mbarrier.arrive.expect_tx.shared.b64 _, [%0], %1;"
                 :: "r"(a), "r"(bytes) : "memory");
}
__device__ __forceinline__ void mbar_wait(uint32_t a, uint32_t parity) {
    asm volatile(
        "{\n\t.reg .pred P;\n\t"
        "W_%=:\n\t"
        "mbarrier.try_wait.parity.acquire.cta.shared::cta.b64 P, [%0], %1, 0x989680;\n\t"
        "@P bra.uni D_%=;\n\t"
        "bra.uni W_%=;\n\t"
        "D_%=:\n\t}"
        :: "r"(a), "r"(parity) : "memory");
}
__device__ __forceinline__ void fence_async() {
    asm volatile("fence.proxy.async.shared::cta;" ::: "memory");
}
__device__ __forceinline__ void ldmat4(uint32_t* r, uint32_t addr) {
    asm volatile("ldmatrix.sync.aligned.m8n8.x4.shared.b16 {%0,%1,%2,%3}, [%4];"
                 : "=r"(r[0]), "=r"(r[1]), "=r"(r[2]), "=r"(r[3]) : "r"(addr));
}
__device__ __forceinline__ void mma16816(float* c, const uint32_t* a,
                                         uint32_t b0, uint32_t b1) {
    asm volatile(
        "mma.sync.aligned.m16n8k16.row.col.f32.bf16.bf16.f32 "
        "{%0,%1,%2,%3}, {%4,%5,%6,%7}, {%8,%9}, {%0,%1,%2,%3};"
        : "+f"(c[0]), "+f"(c[1]), "+f"(c[2]), "+f"(c[3])
        : "r"(a[0]), "r"(a[1]), "r"(a[2]), "r"(a[3]), "r"(b0), "r"(b1));
}

// swizzled granule offset within a 64B row: g in 0..3, row r
__device__ __host__ __forceinline__ uint32_t swz(uint32_t g, uint32_t r) {
    return ((g + ((r >> 1) & 3)) & 3) << 4;
}

// -------------------- HMMA GEMM ---------------------------------------------
// ABULK=true : A chunk-contiguous in gmem (leaf) -> bulk copies.
// ABULK=false: A = h_cat rows (tree mapping), loaded via LDGSTS.
// Split-K: blockIdx.z = split index; kof = z*nk chunks; output goes to
//   C + z*splitE; bias added only by split 0.
template <bool ABULK>
__global__ void __launch_bounds__(256, 2) gemm_mma_kernel(
    const __nv_bfloat16* __restrict__ Ah, const __nv_bfloat16* __restrict__ Al,
    const __nv_bfloat16* __restrict__ Bh, const __nv_bfloat16* __restrict__ Bl,
    const float* __restrict__ bias, float* __restrict__ C,
    int Ntot, long planeB, long planeA, int nk, int tree_lm, int off_prev,
    size_t splitE)
{
    __shared__ uint64_t mbars[2];
    extern __shared__ char smem[];
    const uint32_t sbase = smem_u32(smem);
    const uint32_t mb0 = smem_u32(&mbars[0]);
    const uint32_t mb1 = smem_u32(&mbars[1]);
    const int t = threadIdx.x;
    const int lane = t & 31, wid = t >> 5;
    const int m0 = blockIdx.y * BM, n0 = blockIdx.x * BN;
    const int kof = blockIdx.z * nk;
    C += (size_t)blockIdx.z * splitE;
    const float bscale = (blockIdx.z == 0) ? 1.0f : 0.0f;

    if (t == 0) {
        mbar_init(mb0, 1);
        mbar_init(mb1, 1);
        fence_async();
    }
    __syncthreads();

    // ---------- A loader setup (levels only): rows t>>2 and +64, seg t&3 ----
    const char *pAh0 = nullptr, *pAh1 = nullptr, *pAl0 = nullptr, *pAl1 = nullptr;
    uint32_t dA0 = 0, dA1 = 0;
    if (!ABULK) {
        const int row0 = t >> 2, row1 = row0 + 64;
        const int seg = t & 3;
        const int msk = (1 << tree_lm) - 1;
        const int gr0 = m0 + row0, gr1 = m0 + row1;
        const size_t a0b =
            ((size_t)(gr0 >> tree_lm) * NN + off_prev + 2 * (gr0 & msk)) * H_;
        const size_t a1b =
            ((size_t)(gr1 >> tree_lm) * NN + off_prev + 2 * (gr1 & msk)) * H_;
        pAh0 = (const char*)(Ah + a0b) + seg * 16;
        pAh1 = (const char*)(Ah + a1b) + seg * 16;
        pAl0 = (const char*)(Al + a0b) + seg * 16;
        pAl1 = (const char*)(Al + a1b) + seg * 16;
        dA0 = (uint32_t)row0 * 64 + swz(seg, row0);
        dA1 = (uint32_t)row1 * 64 + swz(seg, row1);
    }

#define LOADS(kk, st) do {                                                    \
        const uint32_t sb_ = sbase + (uint32_t)(st) * STAGE;                  \
        const uint32_t mbar_ = (st) ? mb1 : mb0;                              \
        const int kg_ = kof + (kk);                                           \
        if (!ABULK) {                                                         \
            const size_t gb_ = (size_t)kg_ * 64;                              \
            cp16(sb_ + OFF_AH + dA0, pAh0 + gb_);                             \
            cp16(sb_ + OFF_AH + dA1, pAh1 + gb_);                             \
            cp16(sb_ + OFF_AL + dA0, pAl0 + gb_);                             \
            cp16(sb_ + OFF_AL + dA1, pAl1 + gb_);                             \
            cp_commit();                                                      \
        }                                                                     \
        if (t == 0) {                                                         \
            mbar_expect(mbar_, ABULK ? 32768u : 16384u);                      \
            const long bo_ = (long)kg_ * planeB + (long)n0 * 64;              \
            bulk_cp(sb_ + OFF_BH, (const char*)Bh + bo_, 8192, mbar_);        \
            bulk_cp(sb_ + OFF_BL, (const char*)Bl + bo_, 8192, mbar_);        \
            if (ABULK) {                                                      \
                const long ao_ = (long)kg_ * planeA + (long)m0 * 64;          \
                bulk_cp(sb_ + OFF_AH, (const char*)Ah + ao_, 8192, mbar_);    \
                bulk_cp(sb_ + OFF_AL, (const char*)Al + ao_, 8192, mbar_);    \
            }                                                                 \
        }                                                                     \
    } while (0)

    // ---------- compute setup: 4x2 warp grid, 32x64 warp tile ----------
    const int warp_m = (wid & 3) * 32, warp_n = (wid >> 2) * 64;
    const uint32_t half = (uint32_t)(lane >> 4);
    uint32_t aRow[2], aSw[2], bRow[4], bSw[4];
#pragma unroll
    for (int mi = 0; mi < 2; mi++) {
        const uint32_t R = (uint32_t)(warp_m + mi * 16 + (lane & 15));
        aRow[mi] = R * 64;
        aSw[mi] = (R >> 1) & 3;
    }
#pragma unroll
    for (int g = 0; g < 4; g++) {
        const uint32_t R = (uint32_t)(warp_n + g * 16 + (lane & 15));
        bRow[g] = R * 64;
        bSw[g] = (R >> 1) & 3;
    }

    float acc[2][8][4];
#pragma unroll
    for (int mi = 0; mi < 2; mi++)
#pragma unroll
        for (int nj = 0; nj < 8; nj++)
#pragma unroll
            for (int q = 0; q < 4; q++) acc[mi][nj][q] = 0.0f;

    LOADS(0, 0);
    LOADS(1, 1);

    for (int k = 0; k < nk; k++) {
        if (!ABULK) {
            if (k + 1 < nk) cp_wait<1>();
            else            cp_wait<0>();
        }
        mbar_wait((k & 1) ? mb1 : mb0, (k >> 1) & 1);
        __syncthreads();

        const uint32_t sb = sbase + (uint32_t)(k & 1) * STAGE;
#pragma unroll
        for (int ks = 0; ks < 2; ks++) {
            uint32_t ah[2][4], al[2][4];
#pragma unroll
            for (int mi = 0; mi < 2; mi++) {
                const uint32_t ad = sb + aRow[mi]
                    + ((((uint32_t)(ks << 1) + half + aSw[mi]) & 3) << 4);
                ldmat4(ah[mi], ad + OFF_AH);
                ldmat4(al[mi], ad + OFF_AL);
            }
#pragma unroll
            for (int g = 0; g < 4; g++) {
                uint32_t bh[4], bl[4];
                const uint32_t bd = sb + bRow[g]
                    + ((((uint32_t)(ks << 1) + half + bSw[g]) & 3) << 4);
                ldmat4(bh, bd + OFF_BH);
                ldmat4(bl, bd + OFF_BL);
#pragma unroll
                for (int mi = 0; mi < 2; mi++) {
                    mma16816(acc[mi][2 * g],     ah[mi], bh[0], bh[2]);
                    mma16816(acc[mi][2 * g + 1], ah[mi], bh[1], bh[3]);
                }
#pragma unroll
                for (int mi = 0; mi < 2; mi++) {
                    mma16816(acc[mi][2 * g],     al[mi], bh[0], bh[2]);
                    mma16816(acc[mi][2 * g + 1], al[mi], bh[1], bh[3]);
                }
#pragma unroll
                for (int mi = 0; mi < 2; mi++) {
                    mma16816(acc[mi][2 * g],     ah[mi], bl[0], bl[2]);
                    mma16816(acc[mi][2 * g + 1], ah[mi], bl[1], bl[3]);
                }
            }
        }
        __syncthreads();
        if (k + 2 < nk) LOADS(k + 2, k & 1);
    }

    // ---------- epilogue ----------
    const int er = lane >> 2, ec = (lane & 3) * 2;
#pragma unroll
    for (int mi = 0; mi < 2; mi++) {
        const int rbase = m0 + warp_m + mi * 16 + er;
#pragma unroll
        for (int nj = 0; nj < 8; nj++) {
            const int col = n0 + warp_n + nj * 8 + ec;
            const float b0 = bias[col] * bscale, b1 = bias[col + 1] * bscale;
            float2 v;
            v.x = acc[mi][nj][0] + b0;
            v.y = acc[mi][nj][1] + b1;
            *(float2*)&C[(size_t)rbase * Ntot + col] = v;
            v.x = acc[mi][nj][2] + b0;
            v.y = acc[mi][nj][3] + b1;
            *(float2*)&C[(size_t)(rbase + 8) * Ntot + col] = v;
        }
    }
#undef LOADS
}

// -------------------- cell / epilogue kernels -------------------------------
__device__ __forceinline__ float sigf(float x) { return 1.0f / (1.0f + expf(-x)); }

__device__ __forceinline__ void store_h(size_t ob, float hn) {
    const __nv_bfloat16 hi = __float2bfloat16(hn);
    g_hh[ob] = hi;
    g_hl[ob] = __float2bfloat16(hn - __bfloat162float(hi));
}

__global__ void cell_leaf_kernel(const float* __restrict__ buf)
{
    const size_t idx = (size_t)blockIdx.x * blockDim.x + threadIdx.x;
    if (idx >= (size_t)B_ * LVS * H_) return;
    const int n = (int)(idx & (H_ - 1));
    const size_t r = idx >> 9;
    const float* row = buf + r * TH;
    const float i_ = row[n], o_ = row[n + 512], u_ = row[n + 1024];
    const float cn = sigf(i_) * tanhf(u_);
    const float hn = sigf(o_) * tanhf(cn);
    const int b = (int)(r >> 8), leaf = (int)(r & 255);
    const size_t ob = ((size_t)b * NN + leaf) * H_ + n;
    g_c[ob] = cn;
    store_h(ob, hn);
}

// nsplit partial buffers at stride splitE; split 0 already contains bias.
__global__ void cell_level_kernel(const float* __restrict__ buf,
                                  int lm, int off, int off_prev, int total,
                                  int nsplit, size_t splitE)
{
    const int idx = blockIdx.x * blockDim.x + threadIdx.x;
    if (idx >= total) return;
    const int n = idx & (H_ - 1);
    const int r = idx >> 9;
    const int b = r >> lm;
    const int j = r & ((1 << lm) - 1);
    const size_t base = (size_t)r * NC;
    float i_ = buf[base + n];
    float o_ = buf[base + n + 512];
    float u_ = buf[base + n + 1024];
    float f0 = buf[base + n + 1536];
    float f1 = buf[base + n + 2048];
    for (int s = 1; s < nsplit; s++) {
        const size_t sb = base + (size_t)s * splitE;
        i_ += buf[sb + n];
        o_ += buf[sb + n + 512];
        u_ += buf[sb + n + 1024];
        f0 += buf[sb + n + 1536];
        f1 += buf[sb + n + 2048];
    }
    const size_t cb = ((size_t)b * NN + off_prev + 2 * j) * H_ + n;
    const float cf = sigf(f0) * g_c[cb] + sigf(f1) * g_c[cb + H_];
    const float cn = sigf(i_) * tanhf(u_) + cf;
    const float hn = sigf(o_) * tanhf(cn);
    const size_t ob = ((size_t)b * NN + off + j) * H_ + n;
    g_c[ob] = cn;
    store_h(ob, hn);
}

// -------------------- classifier: one warp per node --------------------------
__global__ void classify_kernel(const float* __restrict__ lw,
                                const float* __restrict__ lb,
                                float* __restrict__ out)
{
    const int gw = (blockIdx.x * blockDim.x + threadIdx.x) >> 5;
    if (gw >= B_ * NN) return;
    const int lane = threadIdx.x & 31;
    const __nv_bfloat162* hh = (const __nv_bfloat162*)(g_hh + (size_t)gw * H_);
    const __nv_bfloat162* hl = (const __nv_bfloat162*)(g_hl + (size_t)gw * H_);
    float acc[5] = {0.f, 0.f, 0.f, 0.f, 0.f};
#pragma unroll
    for (int i = 0; i < 8; i++) {
        const int k2 = lane + 32 * i;                 // bf16x2 index 0..255
        const float2 a = __bfloat1622float2(hh[k2]);
        const float2 b = __bfloat1622float2(hl[k2]);
        const float h0 = a.x + b.x, h1 = a.y + b.y;
#pragma unroll
        for (int c = 0; c < 5; c++) {
            const float2 w = *(const float2*)(lw + (size_t)c * H_ + 2 * k2);
            acc[c] += h0 * w.x + h1 * w.y;
        }
    }
#pragma unroll
    for (int c = 0; c < 5; c++)
#pragma unroll
        for (int off = 16; off > 0; off >>= 1)
            acc[c] += __shfl_xor_sync(0xFFFFFFFF, acc[c], off);
    if (lane < 5)
        out[(size_t)gw * 5 + lane] = acc[lane] + lb[lane];
}

// -------------------- packing / gather (chunked + swizzled) -----------------
__device__ __forceinline__ void split_store(float v, __nv_bfloat16* hi,
                                            __nv_bfloat16* lo, size_t half_idx) {
    const __nv_bfloat16 h = __float2bfloat16(v);
    hi[half_idx] = h;
    lo[half_idx] = __float2bfloat16(v - __bfloat162float(h));
}
__device__ __forceinline__ size_t chunk_off(int row, int k, long plane) {
    const int kc = k >> 5;
    const uint32_t g = ((uint32_t)(k & 31)) >> 3;
    const size_t byte = (size_t)kc * plane + (size_t)row * 64
                      + swz(g, (uint32_t)row) + (size_t)(k & 7) * 2;
    return byte >> 1;   // bf16 index
}

__global__ void pack_wcat_kernel(const float* __restrict__ Uiou,
                                 const float* __restrict__ Uf,
                                 const float* __restrict__ bi,
                                 const float* __restrict__ bf)
{
    const int idx = blockIdx.x * blockDim.x + threadIdx.x;
    if (idx >= NC * 1024) return;
    const int n = idx >> 10, k = idx & 1023;
    const float v = (n < TH) ? Uiou[(size_t)n * 1024 + k]
                             : Uf[(size_t)(n - TH) * 1024 + k];
    split_store(v, g_wch, g_wcl, chunk_off(n, k, PLANE_WC));
    if (k == 0) g_bc[n] = (n < TH) ? bi[n] : bf[n - TH];
}

__global__ void pack_wleaf_kernel(const float* __restrict__ W)
{
    const int idx = blockIdx.x * blockDim.x + threadIdx.x;
    if (idx >= TH * KLF) return;
    const int n = idx / KLF, k = idx - n * KLF;
    const float v = (k < X_) ? W[(size_t)n * X_ + k] : 0.0f;
    split_store(v, g_wlh, g_wll, chunk_off(n, k, PLANE_WL));
}

__global__ void gather_x_kernel(const int* __restrict__ wid,
                                const float* __restrict__ emb)
{
    const int r = blockIdx.x;
    const int c = threadIdx.x;
    if (c >= KLF) return;
    const float v = (c < X_) ? emb[(size_t)wid[r] * X_ + c] : 0.0f;
    split_store(v, g_xh, g_xl, chunk_off(r, c, PLANE_X));
}

// -------------------- launch ------------------------------------------------
extern "C" void kernel_launch(void* const* d_in, const int* in_sizes, int n_in,
                              void* d_out, int out_size)
{
    const int*   wordid  = (const int*)  d_in[0];
    const float* emb     = (const float*)d_in[1];
    const float* W_iou_w = (const float*)d_in[2];
    const float* W_iou_b = (const float*)d_in[3];
    const float* U_iou_w = (const float*)d_in[4];
    const float* U_iou_b = (const float*)d_in[5];
    const float* U_f_w   = (const float*)d_in[6];
    const float* U_f_b   = (const float*)d_in[7];
    const float* lin_w   = (const float*)d_in[8];
    const float* lin_b   = (const float*)d_in[9];
    float* out = (float*)d_out;
    (void)in_sizes; (void)n_in; (void)out_size;

    float *pbuf, *pbc;
    __nv_bfloat16 *phh, *phl, *pxh, *pxl, *pwch, *pwcl, *pwlh, *pwll;
    cudaGetSymbolAddress((void**)&pbuf, g_buf);
    cudaGetSymbolAddress((void**)&pbc,  g_bc);
    cudaGetSymbolAddress((void**)&phh,  g_hh);
    cudaGetSymbolAddress((void**)&phl,  g_hl);
    cudaGetSymbolAddress((void**)&pxh,  g_xh);
    cudaGetSymbolAddress((void**)&pxl,  g_xl);
    cudaGetSymbolAddress((void**)&pwch, g_wch);
    cudaGetSymbolAddress((void**)&pwcl, g_wcl);
    cudaGetSymbolAddress((void**)&pwlh, g_wlh);
    cudaGetSymbolAddress((void**)&pwll, g_wll);

    cudaFuncSetAttribute(gemm_mma_kernel<false>,
                         cudaFuncAttributeMaxDynamicSharedMemorySize, SMEM_BYTES);
    cudaFuncSetAttribute(gemm_mma_kernel<true>,
                         cudaFuncAttributeMaxDynamicSharedMemorySize, SMEM_BYTES);

    // ---- prep ----
    pack_wcat_kernel <<<(NC * 1024 + 255) / 256, 256>>>(U_iou_w, U_f_w,
                                                        U_iou_b, U_f_b);
    pack_wleaf_kernel<<<(TH * KLF + 255) / 256, 256>>>(W_iou_w);
    gather_x_kernel  <<<B_ * LVS, KLF>>>(wordid, emb);

    // ---- leaves: all-bulk GEMM ----
    {
        dim3 g(TH / BN, (B_ * LVS) / BM, 1);   // 12 x 512
        gemm_mma_kernel<true><<<g, 256, SMEM_BYTES>>>(
            pxh, pxl, pwlh, pwll, W_iou_b, pbuf,
            TH, PLANE_WL, PLANE_X, KLF / BK, 0, 0, 0);
        cell_leaf_kernel<<<(B_ * LVS * H_) / 256, 256>>>(pbuf);
    }

    // ---- internal levels: bulk-B, LDGSTS-A GEMM; tuned split-K -------------
    static const int offs[10]   = {0, 256, 384, 448, 480, 496, 504, 508, 510, 511};
    static const int splits[9]  = {0, 1, 1, 1, 2, 4, 4, 8, 8};
    for (int l = 1; l <= 8; l++) {
        const int m = LVS >> l;
        const int M = B_ * m;
        const int lm = 8 - l;
        const int S = splits[l];
        const size_t splitE = (size_t)M * NC;
        dim3 g(NC / BN, M / BM, S);
        gemm_mma_kernel<false><<<g, 256, SMEM_BYTES>>>(
            phh, phl, pwch, pwcl, pbc, pbuf,
            NC, PLANE_WC, 0, (1024 / BK) / S, lm, offs[l - 1], splitE);
        const int total = M * H_;
        cell_level_kernel<<<(total + 255) / 256, 256>>>(pbuf, lm, offs[l],
                                                        offs[l - 1], total,
                                                        S, splitE);
    }

    // ---- classifier: one warp per node ----
    classify_kernel<<<(B_ * NN * 32 + 255) / 256, 256>>>(lin_w, lin_b, out);
}

// round 15
// speedup vs baseline: 1.5998x; 1.1344x over previous
#include <cuda_runtime.h>
#include <cuda_bf16.h>
#include <cstdint>
#include <cstddef>

// ---------------------------------------------------------------------------
// TreeLSTM via mma.sync (HMMA) bf16 GEMM, hi/lo split compensation:
//   C = Ahi*Bhi + Alo*Bhi + Ahi*Blo   (fp32 register accumulation)
// R15 = R14 (best, 4074us) + cells ALSO write h in K-chunked+swizzled planes
//   so every level GEMM runs the all-bulk (ABULK) path: zero LDGSTS.
//   Measured: HMMA rt~8 (leaf tensor=65.2%) -> ~1.1ms of bubbles recoverable.
// ---------------------------------------------------------------------------

#define B_   256
#define LVS  256
#define H_   512
#define X_   300
#define NN   511
#define TH   1536
#define NC   2560
#define KLF  320            // leaf K padded to multiple of 32

#define BM   128
#define BN   128
#define BK   32
// per-stage smem: 4 planes of 8KB (Ah, Al, Bh, Bl), 64B rows, swizzled
#define OFF_AH 0
#define OFF_AL 8192
#define OFF_BH 16384
#define OFF_BL 24576
#define STAGE  32768
#define SMEM_BYTES (2 * STAGE)   // 65536 -> 2 CTAs/SM

// gmem chunk-plane strides (bytes)
#define PLANE_WC  ((long)NC * 64)        // 163840
#define PLANE_WL  ((long)TH * 64)        // 98304
#define PLANE_X   ((long)B_ * LVS * 64)  // 4194304

// -------------------- static scratch ----------------------------------------
__device__ float         g_c  [(size_t)B_ * NN * H_];
__device__ float         g_buf[(size_t)B_ * LVS * TH];
__device__ __nv_bfloat16 g_hh [(size_t)B_ * NN * H_];
__device__ __nv_bfloat16 g_hl [(size_t)B_ * NN * H_];
__device__ __nv_bfloat16 g_ahh[(size_t)32768 * 1024];     // chunked A (next lvl)
__device__ __nv_bfloat16 g_ahl[(size_t)32768 * 1024];
__device__ __nv_bfloat16 g_xh [(size_t)B_ * LVS * KLF];   // chunked+swizzled
__device__ __nv_bfloat16 g_xl [(size_t)B_ * LVS * KLF];
__device__ __nv_bfloat16 g_wch[(size_t)NC * 1024];        // chunked+swizzled
__device__ __nv_bfloat16 g_wcl[(size_t)NC * 1024];
__device__ __nv_bfloat16 g_wlh[(size_t)TH * KLF];         // chunked+swizzled
__device__ __nv_bfloat16 g_wll[(size_t)TH * KLF];
__device__ float         g_bc [NC];

// -------------------- PTX helpers -------------------------------------------
__device__ __forceinline__ uint32_t smem_u32(const void* p) {
    uint32_t a;
    asm("{ .reg .u64 t; cvta.to.shared.u64 t, %1; cvt.u32.u64 %0, t; }"
        : "=r"(a) : "l"(p));
    return a;
}
__device__ __forceinline__ void bulk_cp(uint32_t dst, const void* src,
                                        uint32_t bytes, uint32_t mbar) {
    asm volatile(
        "cp.async.bulk.shared::cta.global.mbarrier::complete_tx::bytes "
        "[%0], [%1], %2, [%3];"
        :: "r"(dst), "l"(src), "r"(bytes), "r"(mbar) : "memory");
}
__device__ __forceinline__ void mbar_init(uint32_t a, uint32_t cnt) {
    asm volatile("mbarrier.init.shared.b64 [%0], %1;" :: "r"(a), "r"(cnt) : "memory");
}
__device__ __forceinline__ void mbar_expect(uint32_t a, uint32_t bytes) {
    asm volatile("mbarrier.arrive.expect_tx.shared.b64 _, [%0], %1;"
                 :: "r"(a), "r"(bytes) : "memory");
}
__device__ __forceinline__ void mbar_wait(uint32_t a, uint32_t parity) {
    asm volatile(
        "{\n\t.reg .pred P;\n\t"
        "W_%=:\n\t"
        "mbarrier.try_wait.parity.acquire.cta.shared::cta.b64 P, [%0], %1, 0x989680;\n\t"
        "@P bra.uni D_%=;\n\t"
        "bra.uni W_%=;\n\t"
        "D_%=:\n\t}"
        :: "r"(a), "r"(parity) : "memory");
}
__device__ __forceinline__ void fence_async() {
    asm volatile("fence.proxy.async.shared::cta;" ::: "memory");
}
__device__ __forceinline__ void ldmat4(uint32_t* r, uint32_t addr) {
    asm volatile("ldmatrix.sync.aligned.m8n8.x4.shared.b16 {%0,%1,%2,%3}, [%4];"
                 : "=r"(r[0]), "=r"(r[1]), "=r"(r[2]), "=r"(r[3]) : "r"(addr));
}
__device__ __forceinline__ void mma16816(float* c, const uint32_t* a,
                                         uint32_t b0, uint32_t b1) {
    asm volatile(
        "mma.sync.aligned.m16n8k16.row.col.f32.bf16.bf16.f32 "
        "{%0,%1,%2,%3}, {%4,%5,%6,%7}, {%8,%9}, {%0,%1,%2,%3};"
        : "+f"(c[0]), "+f"(c[1]), "+f"(c[2]), "+f"(c[3])
        : "r"(a[0]), "r"(a[1]), "r"(a[2]), "r"(a[3]), "r"(b0), "r"(b1));
}

// swizzled granule offset within a 64B row: g in 0..3, row r
__device__ __host__ __forceinline__ uint32_t swz(uint32_t g, uint32_t r) {
    return ((g + ((r >> 1) & 3)) & 3) << 4;
}

// -------------------- HMMA GEMM (all-bulk) ----------------------------------
// A and B both chunk-contiguous in gmem -> 4 bulk copies/chunk, zero LDGSTS.
// Split-K: blockIdx.z = split index; kof = z*nk chunks; output goes to
//   C + z*splitE; bias added only by split 0.
__global__ void __launch_bounds__(256, 2) gemm_mma_kernel(
    const __nv_bfloat16* __restrict__ Ah, const __nv_bfloat16* __restrict__ Al,
    const __nv_bfloat16* __restrict__ Bh, const __nv_bfloat16* __restrict__ Bl,
    const float* __restrict__ bias, float* __restrict__ C,
    int Ntot, long planeB, long planeA, int nk, size_t splitE)
{
    __shared__ uint64_t mbars[2];
    extern __shared__ char smem[];
    const uint32_t sbase = smem_u32(smem);
    const uint32_t mb0 = smem_u32(&mbars[0]);
    const uint32_t mb1 = smem_u32(&mbars[1]);
    const int t = threadIdx.x;
    const int lane = t & 31, wid = t >> 5;
    const int m0 = blockIdx.y * BM, n0 = blockIdx.x * BN;
    const int kof = blockIdx.z * nk;
    C += (size_t)blockIdx.z * splitE;
    const float bscale = (blockIdx.z == 0) ? 1.0f : 0.0f;

    if (t == 0) {
        mbar_init(mb0, 1);
        mbar_init(mb1, 1);
        fence_async();
    }
    __syncthreads();

#define LOADS(kk, st) do {                                                    \
        const uint32_t sb_ = sbase + (uint32_t)(st) * STAGE;                  \
        const uint32_t mbar_ = (st) ? mb1 : mb0;                              \
        const int kg_ = kof + (kk);                                           \
        if (t == 0) {                                                         \
            mbar_expect(mbar_, 32768u);                                       \
            const long bo_ = (long)kg_ * planeB + (long)n0 * 64;              \
            const long ao_ = (long)kg_ * planeA + (long)m0 * 64;              \
            bulk_cp(sb_ + OFF_BH, (const char*)Bh + bo_, 8192, mbar_);        \
            bulk_cp(sb_ + OFF_BL, (const char*)Bl + bo_, 8192, mbar_);        \
            bulk_cp(sb_ + OFF_AH, (const char*)Ah + ao_, 8192, mbar_);        \
            bulk_cp(sb_ + OFF_AL, (const char*)Al + ao_, 8192, mbar_);        \
        }                                                                     \
    } while (0)

    // ---------- compute setup: 4x2 warp grid, 32x64 warp tile ----------
    const int warp_m = (wid & 3) * 32, warp_n = (wid >> 2) * 64;
    const uint32_t half = (uint32_t)(lane >> 4);
    uint32_t aRow[2], aSw[2], bRow[4], bSw[4];
#pragma unroll
    for (int mi = 0; mi < 2; mi++) {
        const uint32_t R = (uint32_t)(warp_m + mi * 16 + (lane & 15));
        aRow[mi] = R * 64;
        aSw[mi] = (R >> 1) & 3;
    }
#pragma unroll
    for (int g = 0; g < 4; g++) {
        const uint32_t R = (uint32_t)(warp_n + g * 16 + (lane & 15));
        bRow[g] = R * 64;
        bSw[g] = (R >> 1) & 3;
    }

    float acc[2][8][4];
#pragma unroll
    for (int mi = 0; mi < 2; mi++)
#pragma unroll
        for (int nj = 0; nj < 8; nj++)
#pragma unroll
            for (int q = 0; q < 4; q++) acc[mi][nj][q] = 0.0f;

    LOADS(0, 0);
    LOADS(1, 1);

    for (int k = 0; k < nk; k++) {
        mbar_wait((k & 1) ? mb1 : mb0, (k >> 1) & 1);
        __syncthreads();

        const uint32_t sb = sbase + (uint32_t)(k & 1) * STAGE;
#pragma unroll
        for (int ks = 0; ks < 2; ks++) {
            uint32_t ah[2][4], al[2][4];
#pragma unroll
            for (int mi = 0; mi < 2; mi++) {
                const uint32_t ad = sb + aRow[mi]
                    + ((((uint32_t)(ks << 1) + half + aSw[mi]) & 3) << 4);
                ldmat4(ah[mi], ad + OFF_AH);
                ldmat4(al[mi], ad + OFF_AL);
            }
#pragma unroll
            for (int g = 0; g < 4; g++) {
                uint32_t bh[4], bl[4];
                const uint32_t bd = sb + bRow[g]
                    + ((((uint32_t)(ks << 1) + half + bSw[g]) & 3) << 4);
                ldmat4(bh, bd + OFF_BH);
                ldmat4(bl, bd + OFF_BL);
#pragma unroll
                for (int mi = 0; mi < 2; mi++) {
                    mma16816(acc[mi][2 * g],     ah[mi], bh[0], bh[2]);
                    mma16816(acc[mi][2 * g + 1], ah[mi], bh[1], bh[3]);
                }
#pragma unroll
                for (int mi = 0; mi < 2; mi++) {
                    mma16816(acc[mi][2 * g],     al[mi], bh[0], bh[2]);
                    mma16816(acc[mi][2 * g + 1], al[mi], bh[1], bh[3]);
                }
#pragma unroll
                for (int mi = 0; mi < 2; mi++) {
                    mma16816(acc[mi][2 * g],     ah[mi], bl[0], bl[2]);
                    mma16816(acc[mi][2 * g + 1], ah[mi], bl[1], bl[3]);
                }
            }
        }
        __syncthreads();
        if (k + 2 < nk) LOADS(k + 2, k & 1);
    }

    // ---------- epilogue ----------
    const int er = lane >> 2, ec = (lane & 3) * 2;
#pragma unroll
    for (int mi = 0; mi < 2; mi++) {
        const int rbase = m0 + warp_m + mi * 16 + er;
#pragma unroll
        for (int nj = 0; nj < 8; nj++) {
            const int col = n0 + warp_n + nj * 8 + ec;
            const float b0 = bias[col] * bscale, b1 = bias[col + 1] * bscale;
            float2 v;
            v.x = acc[mi][nj][0] + b0;
            v.y = acc[mi][nj][1] + b1;
            *(float2*)&C[(size_t)rbase * Ntot + col] = v;
            v.x = acc[mi][nj][2] + b0;
            v.y = acc[mi][nj][3] + b1;
            *(float2*)&C[(size_t)(rbase + 8) * Ntot + col] = v;
        }
    }
#undef LOADS
}

// -------------------- cell / epilogue kernels -------------------------------
__device__ __forceinline__ float sigf(float x) { return 1.0f / (1.0f + expf(-x)); }

__device__ __forceinline__ size_t chunk_off(int row, int k, long plane) {
    const int kc = k >> 5;
    const uint32_t g = ((uint32_t)(k & 31)) >> 3;
    const size_t byte = (size_t)kc * plane + (size_t)row * 64
                      + swz(g, (uint32_t)row) + (size_t)(k & 7) * 2;
    return byte >> 1;   // bf16 index
}

__device__ __forceinline__ void split_store(float v, __nv_bfloat16* hi,
                                            __nv_bfloat16* lo, size_t half_idx) {
    const __nv_bfloat16 h = __float2bfloat16(v);
    hi[half_idx] = h;
    lo[half_idx] = __float2bfloat16(v - __bfloat162float(h));
}

// stores h node-major (classifier) AND chunked (next-level GEMM A) if plane>0
__device__ __forceinline__ void store_h_all(size_t ob, float hn,
                                            int r, int n, long planeNext) {
    const __nv_bfloat16 hi = __float2bfloat16(hn);
    const __nv_bfloat16 lo = __float2bfloat16(hn - __bfloat162float(hi));
    g_hh[ob] = hi;
    g_hl[ob] = lo;
    if (planeNext > 0) {
        const int R = r >> 1;
        const int k = (r & 1) * 512 + n;
        const size_t ci = chunk_off(R, k, planeNext);
        g_ahh[ci] = hi;
        g_ahl[ci] = lo;
    }
}

__global__ void cell_leaf_kernel(const float* __restrict__ buf)
{
    const size_t idx = (size_t)blockIdx.x * blockDim.x + threadIdx.x;
    if (idx >= (size_t)B_ * LVS * H_) return;
    const int n = (int)(idx & (H_ - 1));
    const int r = (int)(idx >> 9);
    const float* row = buf + (size_t)r * TH;
    const float i_ = row[n], o_ = row[n + 512], u_ = row[n + 1024];
    const float cn = sigf(i_) * tanhf(u_);
    const float hn = sigf(o_) * tanhf(cn);
    const int b = r >> 8, leaf = r & 255;
    const size_t ob = ((size_t)b * NN + leaf) * H_ + n;
    g_c[ob] = cn;
    store_h_all(ob, hn, r, n, (long)B_ * 128 * 64);   // level-1 A plane
}

// nsplit partial buffers at stride splitE; split 0 already contains bias.
__global__ void cell_level_kernel(const float* __restrict__ buf,
                                  int lm, int off, int off_prev, int total,
                                  int nsplit, size_t splitE, long planeNext)
{
    const int idx = blockIdx.x * blockDim.x + threadIdx.x;
    if (idx >= total) return;
    const int n = idx & (H_ - 1);
    const int r = idx >> 9;
    const int b = r >> lm;
    const int j = r & ((1 << lm) - 1);
    const size_t base = (size_t)r * NC;
    float i_ = buf[base + n];
    float o_ = buf[base + n + 512];
    float u_ = buf[base + n + 1024];
    float f0 = buf[base + n + 1536];
    float f1 = buf[base + n + 2048];
    for (int s = 1; s < nsplit; s++) {
        const size_t sb = base + (size_t)s * splitE;
        i_ += buf[sb + n];
        o_ += buf[sb + n + 512];
        u_ += buf[sb + n + 1024];
        f0 += buf[sb + n + 1536];
        f1 += buf[sb + n + 2048];
    }
    const size_t cb = ((size_t)b * NN + off_prev + 2 * j) * H_ + n;
    const float cf = sigf(f0) * g_c[cb] + sigf(f1) * g_c[cb + H_];
    const float cn = sigf(i_) * tanhf(u_) + cf;
    const float hn = sigf(o_) * tanhf(cn);
    const size_t ob = ((size_t)b * NN + off + j) * H_ + n;
    g_c[ob] = cn;
    store_h_all(ob, hn, r, n, planeNext);
}

// -------------------- classifier: one warp per node --------------------------
__global__ void classify_kernel(const float* __restrict__ lw,
                                const float* __restrict__ lb,
                                float* __restrict__ out)
{
    const int gw = (blockIdx.x * blockDim.x + threadIdx.x) >> 5;
    if (gw >= B_ * NN) return;
    const int lane = threadIdx.x & 31;
    const __nv_bfloat162* hh = (const __nv_bfloat162*)(g_hh + (size_t)gw * H_);
    const __nv_bfloat162* hl = (const __nv_bfloat162*)(g_hl + (size_t)gw * H_);
    float acc[5] = {0.f, 0.f, 0.f, 0.f, 0.f};
#pragma unroll
    for (int i = 0; i < 8; i++) {
        const int k2 = lane + 32 * i;                 // bf16x2 index 0..255
        const float2 a = __bfloat1622float2(hh[k2]);
        const float2 b = __bfloat1622float2(hl[k2]);
        const float h0 = a.x + b.x, h1 = a.y + b.y;
#pragma unroll
        for (int c = 0; c < 5; c++) {
            const float2 w = *(const float2*)(lw + (size_t)c * H_ + 2 * k2);
            acc[c] += h0 * w.x + h1 * w.y;
        }
    }
#pragma unroll
    for (int c = 0; c < 5; c++)
#pragma unroll
        for (int off = 16; off > 0; off >>= 1)
            acc[c] += __shfl_xor_sync(0xFFFFFFFF, acc[c], off);
    if (lane < 5)
        out[(size_t)gw * 5 + lane] = acc[lane] + lb[lane];
}

// -------------------- packing / gather (chunked + swizzled) -----------------
__global__ void pack_wcat_kernel(const float* __restrict__ Uiou,
                                 const float* __restrict__ Uf,
                                 const float* __restrict__ bi,
                                 const float* __restrict__ bf)
{
    const int idx = blockIdx.x * blockDim.x + threadIdx.x;
    if (idx >= NC * 1024) return;
    const int n = idx >> 10, k = idx & 1023;
    const float v = (n < TH) ? Uiou[(size_t)n * 1024 + k]
                             : Uf[(size_t)(n - TH) * 1024 + k];
    split_store(v, g_wch, g_wcl, chunk_off(n, k, PLANE_WC));
    if (k == 0) g_bc[n] = (n < TH) ? bi[n] : bf[n - TH];
}

__global__ void pack_wleaf_kernel(const float* __restrict__ W)
{
    const int idx = blockIdx.x * blockDim.x + threadIdx.x;
    if (idx >= TH * KLF) return;
    const int n = idx / KLF, k = idx - n * KLF;
    const float v = (k < X_) ? W[(size_t)n * X_ + k] : 0.0f;
    split_store(v, g_wlh, g_wll, chunk_off(n, k, PLANE_WL));
}

__global__ void gather_x_kernel(const int* __restrict__ wid,
                                const float* __restrict__ emb)
{
    const int r = blockIdx.x;
    const int c = threadIdx.x;
    if (c >= KLF) return;
    const float v = (c < X_) ? emb[(size_t)wid[r] * X_ + c] : 0.0f;
    split_store(v, g_xh, g_xl, chunk_off(r, c, PLANE_X));
}

// -------------------- launch ------------------------------------------------
extern "C" void kernel_launch(void* const* d_in, const int* in_sizes, int n_in,
                              void* d_out, int out_size)
{
    const int*   wordid  = (const int*)  d_in[0];
    const float* emb     = (const float*)d_in[1];
    const float* W_iou_w = (const float*)d_in[2];
    const float* W_iou_b = (const float*)d_in[3];
    const float* U_iou_w = (const float*)d_in[4];
    const float* U_iou_b = (const float*)d_in[5];
    const float* U_f_w   = (const float*)d_in[6];
    const float* U_f_b   = (const float*)d_in[7];
    const float* lin_w   = (const float*)d_in[8];
    const float* lin_b   = (const float*)d_in[9];
    float* out = (float*)d_out;
    (void)in_sizes; (void)n_in; (void)out_size;

    float *pbuf, *pbc;
    __nv_bfloat16 *pahh, *pahl, *pxh, *pxl, *pwch, *pwcl, *pwlh, *pwll;
    cudaGetSymbolAddress((void**)&pbuf, g_buf);
    cudaGetSymbolAddress((void**)&pbc,  g_bc);
    cudaGetSymbolAddress((void**)&pahh, g_ahh);
    cudaGetSymbolAddress((void**)&pahl, g_ahl);
    cudaGetSymbolAddress((void**)&pxh,  g_xh);
    cudaGetSymbolAddress((void**)&pxl,  g_xl);
    cudaGetSymbolAddress((void**)&pwch, g_wch);
    cudaGetSymbolAddress((void**)&pwcl, g_wcl);
    cudaGetSymbolAddress((void**)&pwlh, g_wlh);
    cudaGetSymbolAddress((void**)&pwll, g_wll);

    cudaFuncSetAttribute(gemm_mma_kernel,
                         cudaFuncAttributeMaxDynamicSharedMemorySize, SMEM_BYTES);

    // ---- prep ----
    pack_wcat_kernel <<<(NC * 1024 + 255) / 256, 256>>>(U_iou_w, U_f_w,
                                                        U_iou_b, U_f_b);
    pack_wleaf_kernel<<<(TH * KLF + 255) / 256, 256>>>(W_iou_w);
    gather_x_kernel  <<<B_ * LVS, KLF>>>(wordid, emb);

    // ---- leaves: all-bulk GEMM + cell (writes chunked h for level 1) ----
    {
        dim3 g(TH / BN, (B_ * LVS) / BM, 1);   // 12 x 512
        gemm_mma_kernel<<<g, 256, SMEM_BYTES>>>(
            pxh, pxl, pwlh, pwll, W_iou_b, pbuf,
            TH, PLANE_WL, PLANE_X, KLF / BK, 0);
        cell_leaf_kernel<<<(B_ * LVS * H_) / 256, 256>>>(pbuf);
    }

    // ---- internal levels: all-bulk GEMM; tuned split-K ---------------------
    static const int offs[10]   = {0, 256, 384, 448, 480, 496, 504, 508, 510, 511};
    static const int splits[9]  = {0, 1, 1, 1, 2, 4, 4, 8, 8};
    for (int l = 1; l <= 8; l++) {
        const int m = LVS >> l;
        const int M = B_ * m;
        const int lm = 8 - l;
        const int S = splits[l];
        const size_t splitE = (size_t)M * NC;
        const long planeA = (long)M * 64;              // this level's A plane
        const long planeNext = (l < 8) ? (long)(M / 2) * 64 : 0;
        dim3 g(NC / BN, M / BM, S);
        gemm_mma_kernel<<<g, 256, SMEM_BYTES>>>(
            pahh, pahl, pwch, pwcl, pbc, pbuf,
            NC, PLANE_WC, planeA, (1024 / BK) / S, splitE);
        const int total = M * H_;
        cell_level_kernel<<<(total + 255) / 256, 256>>>(pbuf, lm, offs[l],
                                                        offs[l - 1], total,
                                                        S, splitE, planeNext);
    }

    // ---- classifier: one warp per node ----
    classify_kernel<<<(B_ * NN * 32 + 255) / 256, 256>>>(lin_w, lin_b, out);
}

// round 16
// speedup vs baseline: 1.6001x; 1.0002x over previous
#include <cuda_runtime.h>
#include <cuda_bf16.h>
#include <cstdint>
#include <cstddef>

// ---------------------------------------------------------------------------
// TreeLSTM via mma.sync (HMMA) bf16 GEMM, hi/lo split compensation:
//   C = Ahi*Bhi + Alo*Bhi + Ahi*Blo   (fp32 register accumulation)
// R16 = R15 (best, 3591us) + in-warp software pipelining of B-fragment
//   ldmatrix (double-buffered one g-group ahead) to remove the ~30cyc
//   LDSM->HMMA RAW stall at the head of every g-group (8/chunk/warp).
// ---------------------------------------------------------------------------

#define B_   256
#define LVS  256
#define H_   512
#define X_   300
#define NN   511
#define TH   1536
#define NC   2560
#define KLF  320            // leaf K padded to multiple of 32

#define BM   128
#define BN   128
#define BK   32
// per-stage smem: 4 planes of 8KB (Ah, Al, Bh, Bl), 64B rows, swizzled
#define OFF_AH 0
#define OFF_AL 8192
#define OFF_BH 16384
#define OFF_BL 24576
#define STAGE  32768
#define SMEM_BYTES (2 * STAGE)   // 65536 -> 2 CTAs/SM

// gmem chunk-plane strides (bytes)
#define PLANE_WC  ((long)NC * 64)        // 163840
#define PLANE_WL  ((long)TH * 64)        // 98304
#define PLANE_X   ((long)B_ * LVS * 64)  // 4194304

// -------------------- static scratch ----------------------------------------
__device__ float         g_c  [(size_t)B_ * NN * H_];
__device__ float         g_buf[(size_t)B_ * LVS * TH];
__device__ __nv_bfloat16 g_hh [(size_t)B_ * NN * H_];
__device__ __nv_bfloat16 g_hl [(size_t)B_ * NN * H_];
__device__ __nv_bfloat16 g_ahh[(size_t)32768 * 1024];     // chunked A (next lvl)
__device__ __nv_bfloat16 g_ahl[(size_t)32768 * 1024];
__device__ __nv_bfloat16 g_xh [(size_t)B_ * LVS * KLF];   // chunked+swizzled
__device__ __nv_bfloat16 g_xl [(size_t)B_ * LVS * KLF];
__device__ __nv_bfloat16 g_wch[(size_t)NC * 1024];        // chunked+swizzled
__device__ __nv_bfloat16 g_wcl[(size_t)NC * 1024];
__device__ __nv_bfloat16 g_wlh[(size_t)TH * KLF];         // chunked+swizzled
__device__ __nv_bfloat16 g_wll[(size_t)TH * KLF];
__device__ float         g_bc [NC];

// -------------------- PTX helpers -------------------------------------------
__device__ __forceinline__ uint32_t smem_u32(const void* p) {
    uint32_t a;
    asm("{ .reg .u64 t; cvta.to.shared.u64 t, %1; cvt.u32.u64 %0, t; }"
        : "=r"(a) : "l"(p));
    return a;
}
__device__ __forceinline__ void bulk_cp(uint32_t dst, const void* src,
                                        uint32_t bytes, uint32_t mbar) {
    asm volatile(
        "cp.async.bulk.shared::cta.global.mbarrier::complete_tx::bytes "
        "[%0], [%1], %2, [%3];"
        :: "r"(dst), "l"(src), "r"(bytes), "r"(mbar) : "memory");
}
__device__ __forceinline__ void mbar_init(uint32_t a, uint32_t cnt) {
    asm volatile("mbarrier.init.shared.b64 [%0], %1;" :: "r"(a), "r"(cnt) : "memory");
}
__device__ __forceinline__ void mbar_expect(uint32_t a, uint32_t bytes) {
    asm volatile("mbarrier.arrive.expect_tx.shared.b64 _, [%0], %1;"
                 :: "r"(a), "r"(bytes) : "memory");
}
__device__ __forceinline__ void mbar_wait(uint32_t a, uint32_t parity) {
    asm volatile(
        "{\n\t.reg .pred P;\n\t"
        "W_%=:\n\t"
        "mbarrier.try_wait.parity.acquire.cta.shared::cta.b64 P, [%0], %1, 0x989680;\n\t"
        "@P bra.uni D_%=;\n\t"
        "bra.uni W_%=;\n\t"
        "D_%=:\n\t}"
        :: "r"(a), "r"(parity) : "memory");
}
__device__ __forceinline__ void fence_async() {
    asm volatile("fence.proxy.async.shared::cta;" ::: "memory");
}
__device__ __forceinline__ void ldmat4(uint32_t* r, uint32_t addr) {
    asm volatile("ldmatrix.sync.aligned.m8n8.x4.shared.b16 {%0,%1,%2,%3}, [%4];"
                 : "=r"(r[0]), "=r"(r[1]), "=r"(r[2]), "=r"(r[3]) : "r"(addr));
}
__device__ __forceinline__ void mma16816(float* c, const uint32_t* a,
                                         uint32_t b0, uint32_t b1) {
    asm volatile(
        "mma.sync.aligned.m16n8k16.row.col.f32.bf16.bf16.f32 "
        "{%0,%1,%2,%3}, {%4,%5,%6,%7}, {%8,%9}, {%0,%1,%2,%3};"
        : "+f"(c[0]), "+f"(c[1]), "+f"(c[2]), "+f"(c[3])
        : "r"(a[0]), "r"(a[1]), "r"(a[2]), "r"(a[3]), "r"(b0), "r"(b1));
}

// swizzled granule offset within a 64B row: g in 0..3, row r
__device__ __host__ __forceinline__ uint32_t swz(uint32_t g, uint32_t r) {
    return ((g + ((r >> 1) & 3)) & 3) << 4;
}

// -------------------- HMMA GEMM (all-bulk, B-prefetch pipelined) ------------
// A and B both chunk-contiguous in gmem -> 4 bulk copies/chunk, zero LDGSTS.
// Split-K: blockIdx.z = split index; kof = z*nk chunks; output goes to
//   C + z*splitE; bias added only by split 0.
__global__ void __launch_bounds__(256, 2) gemm_mma_kernel(
    const __nv_bfloat16* __restrict__ Ah, const __nv_bfloat16* __restrict__ Al,
    const __nv_bfloat16* __restrict__ Bh, const __nv_bfloat16* __restrict__ Bl,
    const float* __restrict__ bias, float* __restrict__ C,
    int Ntot, long planeB, long planeA, int nk, size_t splitE)
{
    __shared__ uint64_t mbars[2];
    extern __shared__ char smem[];
    const uint32_t sbase = smem_u32(smem);
    const uint32_t mb0 = smem_u32(&mbars[0]);
    const uint32_t mb1 = smem_u32(&mbars[1]);
    const int t = threadIdx.x;
    const int lane = t & 31, wid = t >> 5;
    const int m0 = blockIdx.y * BM, n0 = blockIdx.x * BN;
    const int kof = blockIdx.z * nk;
    C += (size_t)blockIdx.z * splitE;
    const float bscale = (blockIdx.z == 0) ? 1.0f : 0.0f;

    if (t == 0) {
        mbar_init(mb0, 1);
        mbar_init(mb1, 1);
        fence_async();
    }
    __syncthreads();

#define LOADS(kk, st) do {                                                    \
        const uint32_t sb_ = sbase + (uint32_t)(st) * STAGE;                  \
        const uint32_t mbar_ = (st) ? mb1 : mb0;                              \
        const int kg_ = kof + (kk);                                           \
        if (t == 0) {                                                         \
            mbar_expect(mbar_, 32768u);                                       \
            const long bo_ = (long)kg_ * planeB + (long)n0 * 64;              \
            const long ao_ = (long)kg_ * planeA + (long)m0 * 64;              \
            bulk_cp(sb_ + OFF_BH, (const char*)Bh + bo_, 8192, mbar_);        \
            bulk_cp(sb_ + OFF_BL, (const char*)Bl + bo_, 8192, mbar_);        \
            bulk_cp(sb_ + OFF_AH, (const char*)Ah + ao_, 8192, mbar_);        \
            bulk_cp(sb_ + OFF_AL, (const char*)Al + ao_, 8192, mbar_);        \
        }                                                                     \
    } while (0)

    // ---------- compute setup: 4x2 warp grid, 32x64 warp tile ----------
    const int warp_m = (wid & 3) * 32, warp_n = (wid >> 2) * 64;
    const uint32_t half = (uint32_t)(lane >> 4);
    uint32_t aRow[2], aSw[2], bRow[4], bSw[4];
#pragma unroll
    for (int mi = 0; mi < 2; mi++) {
        const uint32_t R = (uint32_t)(warp_m + mi * 16 + (lane & 15));
        aRow[mi] = R * 64;
        aSw[mi] = (R >> 1) & 3;
    }
#pragma unroll
    for (int g = 0; g < 4; g++) {
        const uint32_t R = (uint32_t)(warp_n + g * 16 + (lane & 15));
        bRow[g] = R * 64;
        bSw[g] = (R >> 1) & 3;
    }

    float acc[2][8][4];
#pragma unroll
    for (int mi = 0; mi < 2; mi++)
#pragma unroll
        for (int nj = 0; nj < 8; nj++)
#pragma unroll
            for (int q = 0; q < 4; q++) acc[mi][nj][q] = 0.0f;

    LOADS(0, 0);
    LOADS(1, 1);

    for (int k = 0; k < nk; k++) {
        mbar_wait((k & 1) ? mb1 : mb0, (k >> 1) & 1);
        __syncthreads();

        const uint32_t sb = sbase + (uint32_t)(k & 1) * STAGE;
#pragma unroll
        for (int ks = 0; ks < 2; ks++) {
            uint32_t ah[2][4], al[2][4];
#pragma unroll
            for (int mi = 0; mi < 2; mi++) {
                const uint32_t ad = sb + aRow[mi]
                    + ((((uint32_t)(ks << 1) + half + aSw[mi]) & 3) << 4);
                ldmat4(ah[mi], ad + OFF_AH);
                ldmat4(al[mi], ad + OFF_AL);
            }
            // double-buffered B fragments: prefetch g+1 before g's HMMAs
            uint32_t bh[2][4], bl[2][4];
            {
                const uint32_t bd0 = sb + bRow[0]
                    + ((((uint32_t)(ks << 1) + half + bSw[0]) & 3) << 4);
                ldmat4(bh[0], bd0 + OFF_BH);
                ldmat4(bl[0], bd0 + OFF_BL);
            }
#pragma unroll
            for (int g = 0; g < 4; g++) {
                const int cur = g & 1, nxt = cur ^ 1;
                if (g < 3) {
                    const uint32_t bd = sb + bRow[g + 1]
                        + ((((uint32_t)(ks << 1) + half + bSw[g + 1]) & 3) << 4);
                    ldmat4(bh[nxt], bd + OFF_BH);
                    ldmat4(bl[nxt], bd + OFF_BL);
                }
#pragma unroll
                for (int mi = 0; mi < 2; mi++) {
                    mma16816(acc[mi][2 * g],     ah[mi], bh[cur][0], bh[cur][2]);
                    mma16816(acc[mi][2 * g + 1], ah[mi], bh[cur][1], bh[cur][3]);
                }
#pragma unroll
                for (int mi = 0; mi < 2; mi++) {
                    mma16816(acc[mi][2 * g],     al[mi], bh[cur][0], bh[cur][2]);
                    mma16816(acc[mi][2 * g + 1], al[mi], bh[cur][1], bh[cur][3]);
                }
#pragma unroll
                for (int mi = 0; mi < 2; mi++) {
                    mma16816(acc[mi][2 * g],     ah[mi], bl[cur][0], bl[cur][2]);
                    mma16816(acc[mi][2 * g + 1], ah[mi], bl[cur][1], bl[cur][3]);
                }
            }
        }
        __syncthreads();
        if (k + 2 < nk) LOADS(k + 2, k & 1);
    }

    // ---------- epilogue ----------
    const int er = lane >> 2, ec = (lane & 3) * 2;
#pragma unroll
    for (int mi = 0; mi < 2; mi++) {
        const int rbase = m0 + warp_m + mi * 16 + er;
#pragma unroll
        for (int nj = 0; nj < 8; nj++) {
            const int col = n0 + warp_n + nj * 8 + ec;
            const float b0 = bias[col] * bscale, b1 = bias[col + 1] * bscale;
            float2 v;
            v.x = acc[mi][nj][0] + b0;
            v.y = acc[mi][nj][1] + b1;
            *(float2*)&C[(size_t)rbase * Ntot + col] = v;
            v.x = acc[mi][nj][2] + b0;
            v.y = acc[mi][nj][3] + b1;
            *(float2*)&C[(size_t)(rbase + 8) * Ntot + col] = v;
        }
    }
#undef LOADS
}

// -------------------- cell / epilogue kernels -------------------------------
__device__ __forceinline__ float sigf(float x) { return 1.0f / (1.0f + expf(-x)); }

__device__ __forceinline__ size_t chunk_off(int row, int k, long plane) {
    const int kc = k >> 5;
    const uint32_t g = ((uint32_t)(k & 31)) >> 3;
    const size_t byte = (size_t)kc * plane + (size_t)row * 64
                      + swz(g, (uint32_t)row) + (size_t)(k & 7) * 2;
    return byte >> 1;   // bf16 index
}

__device__ __forceinline__ void split_store(float v, __nv_bfloat16* hi,
                                            __nv_bfloat16* lo, size_t half_idx) {
    const __nv_bfloat16 h = __float2bfloat16(v);
    hi[half_idx] = h;
    lo[half_idx] = __float2bfloat16(v - __bfloat162float(h));
}

// stores h node-major (classifier) AND chunked (next-level GEMM A) if plane>0
__device__ __forceinline__ void store_h_all(size_t ob, float hn,
                                            int r, int n, long planeNext) {
    const __nv_bfloat16 hi = __float2bfloat16(hn);
    const __nv_bfloat16 lo = __float2bfloat16(hn - __bfloat162float(hi));
    g_hh[ob] = hi;
    g_hl[ob] = lo;
    if (planeNext > 0) {
        const int R = r >> 1;
        const int k = (r & 1) * 512 + n;
        const size_t ci = chunk_off(R, k, planeNext);
        g_ahh[ci] = hi;
        g_ahl[ci] = lo;
    }
}

__global__ void cell_leaf_kernel(const float* __restrict__ buf)
{
    const size_t idx = (size_t)blockIdx.x * blockDim.x + threadIdx.x;
    if (idx >= (size_t)B_ * LVS * H_) return;
    const int n = (int)(idx & (H_ - 1));
    const int r = (int)(idx >> 9);
    const float* row = buf + (size_t)r * TH;
    const float i_ = row[n], o_ = row[n + 512], u_ = row[n + 1024];
    const float cn = sigf(i_) * tanhf(u_);
    const float hn = sigf(o_) * tanhf(cn);
    const int b = r >> 8, leaf = r & 255;
    const size_t ob = ((size_t)b * NN + leaf) * H_ + n;
    g_c[ob] = cn;
    store_h_all(ob, hn, r, n, (long)B_ * 128 * 64);   // level-1 A plane
}

// nsplit partial buffers at stride splitE; split 0 already contains bias.
__global__ void cell_level_kernel(const float* __restrict__ buf,
                                  int lm, int off, int off_prev, int total,
                                  int nsplit, size_t splitE, long planeNext)
{
    const int idx = blockIdx.x * blockDim.x + threadIdx.x;
    if (idx >= total) return;
    const int n = idx & (H_ - 1);
    const int r = idx >> 9;
    const int b = r >> lm;
    const int j = r & ((1 << lm) - 1);
    const size_t base = (size_t)r * NC;
    float i_ = buf[base + n];
    float o_ = buf[base + n + 512];
    float u_ = buf[base + n + 1024];
    float f0 = buf[base + n + 1536];
    float f1 = buf[base + n + 2048];
    for (int s = 1; s < nsplit; s++) {
        const size_t sb = base + (size_t)s * splitE;
        i_ += buf[sb + n];
        o_ += buf[sb + n + 512];
        u_ += buf[sb + n + 1024];
        f0 += buf[sb + n + 1536];
        f1 += buf[sb + n + 2048];
    }
    const size_t cb = ((size_t)b * NN + off_prev + 2 * j) * H_ + n;
    const float cf = sigf(f0) * g_c[cb] + sigf(f1) * g_c[cb + H_];
    const float cn = sigf(i_) * tanhf(u_) + cf;
    const float hn = sigf(o_) * tanhf(cn);
    const size_t ob = ((size_t)b * NN + off + j) * H_ + n;
    g_c[ob] = cn;
    store_h_all(ob, hn, r, n, planeNext);
}

// -------------------- classifier: one warp per node --------------------------
__global__ void classify_kernel(const float* __restrict__ lw,
                                const float* __restrict__ lb,
                                float* __restrict__ out)
{
    const int gw = (blockIdx.x * blockDim.x + threadIdx.x) >> 5;
    if (gw >= B_ * NN) return;
    const int lane = threadIdx.x & 31;
    const __nv_bfloat162* hh = (const __nv_bfloat162*)(g_hh + (size_t)gw * H_);
    const __nv_bfloat162* hl = (const __nv_bfloat162*)(g_hl + (size_t)gw * H_);
    float acc[5] = {0.f, 0.f, 0.f, 0.f, 0.f};
#pragma unroll
    for (int i = 0; i < 8; i++) {
        const int k2 = lane + 32 * i;                 // bf16x2 index 0..255
        const float2 a = __bfloat1622float2(hh[k2]);
        const float2 b = __bfloat1622float2(hl[k2]);
        const float h0 = a.x + b.x, h1 = a.y + b.y;
#pragma unroll
        for (int c = 0; c < 5; c++) {
            const float2 w = *(const float2*)(lw + (size_t)c * H_ + 2 * k2);
            acc[c] += h0 * w.x + h1 * w.y;
        }
    }
#pragma unroll
    for (int c = 0; c < 5; c++)
#pragma unroll
        for (int off = 16; off > 0; off >>= 1)
            acc[c] += __shfl_xor_sync(0xFFFFFFFF, acc[c], off);
    if (lane < 5)
        out[(size_t)gw * 5 + lane] = acc[lane] + lb[lane];
}

// -------------------- packing / gather (chunked + swizzled) -----------------
__global__ void pack_wcat_kernel(const float* __restrict__ Uiou,
                                 const float* __restrict__ Uf,
                                 const float* __restrict__ bi,
                                 const float* __restrict__ bf)
{
    const int idx = blockIdx.x * blockDim.x + threadIdx.x;
    if (idx >= NC * 1024) return;
    const int n = idx >> 10, k = idx & 1023;
    const float v = (n < TH) ? Uiou[(size_t)n * 1024 + k]
                             : Uf[(size_t)(n - TH) * 1024 + k];
    split_store(v, g_wch, g_wcl, chunk_off(n, k, PLANE_WC));
    if (k == 0) g_bc[n] = (n < TH) ? bi[n] : bf[n - TH];
}

__global__ void pack_wleaf_kernel(const float* __restrict__ W)
{
    const int idx = blockIdx.x * blockDim.x + threadIdx.x;
    if (idx >= TH * KLF) return;
    const int n = idx / KLF, k = idx - n * KLF;
    const float v = (k < X_) ? W[(size_t)n * X_ + k] : 0.0f;
    split_store(v, g_wlh, g_wll, chunk_off(n, k, PLANE_WL));
}

__global__ void gather_x_kernel(const int* __restrict__ wid,
                                const float* __restrict__ emb)
{
    const int r = blockIdx.x;
    const int c = threadIdx.x;
    if (c >= KLF) return;
    const float v = (c < X_) ? emb[(size_t)wid[r] * X_ + c] : 0.0f;
    split_store(v, g_xh, g_xl, chunk_off(r, c, PLANE_X));
}

// -------------------- launch ------------------------------------------------
extern "C" void kernel_launch(void* const* d_in, const int* in_sizes, int n_in,
                              void* d_out, int out_size)
{
    const int*   wordid  = (const int*)  d_in[0];
    const float* emb     = (const float*)d_in[1];
    const float* W_iou_w = (const float*)d_in[2];
    const float* W_iou_b = (const float*)d_in[3];
    const float* U_iou_w = (const float*)d_in[4];
    const float* U_iou_b = (const float*)d_in[5];
    const float* U_f_w   = (const float*)d_in[6];
    const float* U_f_b   = (const float*)d_in[7];
    const float* lin_w   = (const float*)d_in[8];
    const float* lin_b   = (const float*)d_in[9];
    float* out = (float*)d_out;
    (void)in_sizes; (void)n_in; (void)out_size;

    float *pbuf, *pbc;
    __nv_bfloat16 *pahh, *pahl, *pxh, *pxl, *pwch, *pwcl, *pwlh, *pwll;
    cudaGetSymbolAddress((void**)&pbuf, g_buf);
    cudaGetSymbolAddress((void**)&pbc,  g_bc);
    cudaGetSymbolAddress((void**)&pahh, g_ahh);
    cudaGetSymbolAddress((void**)&pahl, g_ahl);
    cudaGetSymbolAddress((void**)&pxh,  g_xh);
    cudaGetSymbolAddress((void**)&pxl,  g_xl);
    cudaGetSymbolAddress((void**)&pwch, g_wch);
    cudaGetSymbolAddress((void**)&pwcl, g_wcl);
    cudaGetSymbolAddress((void**)&pwlh, g_wlh);
    cudaGetSymbolAddress((void**)&pwll, g_wll);

    cudaFuncSetAttribute(gemm_mma_kernel,
                         cudaFuncAttributeMaxDynamicSharedMemorySize, SMEM_BYTES);

    // ---- prep ----
    pack_wcat_kernel <<<(NC * 1024 + 255) / 256, 256>>>(U_iou_w, U_f_w,
                                                        U_iou_b, U_f_b);
    pack_wleaf_kernel<<<(TH * KLF + 255) / 256, 256>>>(W_iou_w);
    gather_x_kernel  <<<B_ * LVS, KLF>>>(wordid, emb);

    // ---- leaves: all-bulk GEMM + cell (writes chunked h for level 1) ----
    {
        dim3 g(TH / BN, (B_ * LVS) / BM, 1);   // 12 x 512
        gemm_mma_kernel<<<g, 256, SMEM_BYTES>>>(
            pxh, pxl, pwlh, pwll, W_iou_b, pbuf,
            TH, PLANE_WL, PLANE_X, KLF / BK, 0);
        cell_leaf_kernel<<<(B_ * LVS * H_) / 256, 256>>>(pbuf);
    }

    // ---- internal levels: all-bulk GEMM; tuned split-K ---------------------
    static const int offs[10]   = {0, 256, 384, 448, 480, 496, 504, 508, 510, 511};
    static const int splits[9]  = {0, 1, 1, 1, 2, 4, 4, 8, 8};
    for (int l = 1; l <= 8; l++) {
        const int m = LVS >> l;
        const int M = B_ * m;
        const int lm = 8 - l;
        const int S = splits[l];
        const size_t splitE = (size_t)M * NC;
        const long planeA = (long)M * 64;              // this level's A plane
        const long planeNext = (l < 8) ? (long)(M / 2) * 64 : 0;
        dim3 g(NC / BN, M / BM, S);
        gemm_mma_kernel<<<g, 256, SMEM_BYTES>>>(
            pahh, pahl, pwch, pwcl, pbc, pbuf,
            NC, PLANE_WC, planeA, (1024 / BK) / S, splitE);
        const int total = M * H_;
        cell_level_kernel<<<(total + 255) / 256, 256>>>(pbuf, lm, offs[l],
                                                        offs[l - 1], total,
                                                        S, splitE, planeNext);
    }

    // ---- classifier: one warp per node ----
    classify_kernel<<<(B_ * NN * 32 + 255) / 256, 256>>>(lin_w, lin_b, out);
}

// round 17
// speedup vs baseline: 1.6569x; 1.0355x over previous
#include <cuda_runtime.h>
#include <cuda_bf16.h>
#include <cstdint>
#include <cstddef>

// ---------------------------------------------------------------------------
// TreeLSTM via mma.sync (HMMA) bf16 GEMM, hi/lo split compensation:
//   C = Ahi*Bhi + Alo*Bhi + Ahi*Blo   (fp32 register accumulation)
// R17 = R16 (3590us) +
//   * NST=3 pipeline with ONE __syncthreads per chunk (copy window 2 chunks)
//   * 2-wide vectorized cell kernels (float2 / bf16x2, incl. chunked store)
// ---------------------------------------------------------------------------

#define B_   256
#define LVS  256
#define H_   512
#define X_   300
#define NN   511
#define TH   1536
#define NC   2560
#define KLF  320            // leaf K padded to multiple of 32

#define BM   128
#define BN   128
#define BK   32
// per-stage smem: 4 planes of 8KB (Ah, Al, Bh, Bl), 64B rows, swizzled
#define OFF_AH 0
#define OFF_AL 8192
#define OFF_BH 16384
#define OFF_BL 24576
#define STAGE  32768
#define NST    3
#define SMEM_BYTES (NST * STAGE)   // 98304 -> 2 CTAs/SM

// gmem chunk-plane strides (bytes)
#define PLANE_WC  ((long)NC * 64)        // 163840
#define PLANE_WL  ((long)TH * 64)        // 98304
#define PLANE_X   ((long)B_ * LVS * 64)  // 4194304

// -------------------- static scratch ----------------------------------------
__device__ float         g_c  [(size_t)B_ * NN * H_];
__device__ float         g_buf[(size_t)B_ * LVS * TH];
__device__ __nv_bfloat16 g_hh [(size_t)B_ * NN * H_];
__device__ __nv_bfloat16 g_hl [(size_t)B_ * NN * H_];
__device__ __nv_bfloat16 g_ahh[(size_t)32768 * 1024];     // chunked A (next lvl)
__device__ __nv_bfloat16 g_ahl[(size_t)32768 * 1024];
__device__ __nv_bfloat16 g_xh [(size_t)B_ * LVS * KLF];   // chunked+swizzled
__device__ __nv_bfloat16 g_xl [(size_t)B_ * LVS * KLF];
__device__ __nv_bfloat16 g_wch[(size_t)NC * 1024];        // chunked+swizzled
__device__ __nv_bfloat16 g_wcl[(size_t)NC * 1024];
__device__ __nv_bfloat16 g_wlh[(size_t)TH * KLF];         // chunked+swizzled
__device__ __nv_bfloat16 g_wll[(size_t)TH * KLF];
__device__ float         g_bc [NC];

// -------------------- PTX helpers -------------------------------------------
__device__ __forceinline__ uint32_t smem_u32(const void* p) {
    uint32_t a;
    asm("{ .reg .u64 t; cvta.to.shared.u64 t, %1; cvt.u32.u64 %0, t; }"
        : "=r"(a) : "l"(p));
    return a;
}
__device__ __forceinline__ void bulk_cp(uint32_t dst, const void* src,
                                        uint32_t bytes, uint32_t mbar) {
    asm volatile(
        "cp.async.bulk.shared::cta.global.mbarrier::complete_tx::bytes "
        "[%0], [%1], %2, [%3];"
        :: "r"(dst), "l"(src), "r"(bytes), "r"(mbar) : "memory");
}
__device__ __forceinline__ void mbar_init(uint32_t a, uint32_t cnt) {
    asm volatile("mbarrier.init.shared.b64 [%0], %1;" :: "r"(a), "r"(cnt) : "memory");
}
__device__ __forceinline__ void mbar_expect(uint32_t a, uint32_t bytes) {
    asm volatile("mbarrier.arrive.expect_tx.shared.b64 _, [%0], %1;"
                 :: "r"(a), "r"(bytes) : "memory");
}
__device__ __forceinline__ void mbar_wait(uint32_t a, uint32_t parity) {
    asm volatile(
        "{\n\t.reg .pred P;\n\t"
        "W_%=:\n\t"
        "mbarrier.try_wait.parity.acquire.cta.shared::cta.b64 P, [%0], %1, 0x989680;\n\t"
        "@P bra.uni D_%=;\n\t"
        "bra.uni W_%=;\n\t"
        "D_%=:\n\t}"
        :: "r"(a), "r"(parity) : "memory");
}
__device__ __forceinline__ void fence_async() {
    asm volatile("fence.proxy.async.shared::cta;" ::: "memory");
}
__device__ __forceinline__ void ldmat4(uint32_t* r, uint32_t addr) {
    asm volatile("ldmatrix.sync.aligned.m8n8.x4.shared.b16 {%0,%1,%2,%3}, [%4];"
                 : "=r"(r[0]), "=r"(r[1]), "=r"(r[2]), "=r"(r[3]) : "r"(addr));
}
__device__ __forceinline__ void mma16816(float* c, const uint32_t* a,
                                         uint32_t b0, uint32_t b1) {
    asm volatile(
        "mma.sync.aligned.m16n8k16.row.col.f32.bf16.bf16.f32 "
        "{%0,%1,%2,%3}, {%4,%5,%6,%7}, {%8,%9}, {%0,%1,%2,%3};"
        : "+f"(c[0]), "+f"(c[1]), "+f"(c[2]), "+f"(c[3])
        : "r"(a[0]), "r"(a[1]), "r"(a[2]), "r"(a[3]), "r"(b0), "r"(b1));
}

// swizzled granule offset within a 64B row: g in 0..3, row r
__device__ __host__ __forceinline__ uint32_t swz(uint32_t g, uint32_t r) {
    return ((g + ((r >> 1) & 3)) & 3) << 4;
}

// -------------------- HMMA GEMM (all-bulk, 3-stage, 1 barrier/chunk) --------
// A and B both chunk-contiguous in gmem -> 4 bulk copies/chunk, zero LDGSTS.
// Split-K: blockIdx.z = split index; kof = z*nk chunks; output goes to
//   C + z*splitE; bias added only by split 0.
__global__ void __launch_bounds__(256, 2) gemm_mma_kernel(
    const __nv_bfloat16* __restrict__ Ah, const __nv_bfloat16* __restrict__ Al,
    const __nv_bfloat16* __restrict__ Bh, const __nv_bfloat16* __restrict__ Bl,
    const float* __restrict__ bias, float* __restrict__ C,
    int Ntot, long planeB, long planeA, int nk, size_t splitE)
{
    __shared__ uint64_t mbars[NST];
    extern __shared__ char smem[];
    const uint32_t sbase = smem_u32(smem);
    uint32_t mb[NST];
#pragma unroll
    for (int i = 0; i < NST; i++) mb[i] = smem_u32(&mbars[i]);
    const int t = threadIdx.x;
    const int lane = t & 31, wid = t >> 5;
    const int m0 = blockIdx.y * BM, n0 = blockIdx.x * BN;
    const int kof = blockIdx.z * nk;
    C += (size_t)blockIdx.z * splitE;
    const float bscale = (blockIdx.z == 0) ? 1.0f : 0.0f;

    if (t == 0) {
#pragma unroll
        for (int i = 0; i < NST; i++) mbar_init(mb[i], 1);
        fence_async();
    }
    __syncthreads();

#define LOADS(kk, st) do {                                                    \
        const uint32_t sb_ = sbase + (uint32_t)(st) * STAGE;                  \
        const uint32_t mbar_ = mb[(st)];                                      \
        const int kg_ = kof + (kk);                                           \
        if (t == 0) {                                                         \
            mbar_expect(mbar_, 32768u);                                       \
            const long bo_ = (long)kg_ * planeB + (long)n0 * 64;              \
            const long ao_ = (long)kg_ * planeA + (long)m0 * 64;              \
            bulk_cp(sb_ + OFF_BH, (const char*)Bh + bo_, 8192, mbar_);        \
            bulk_cp(sb_ + OFF_BL, (const char*)Bl + bo_, 8192, mbar_);        \
            bulk_cp(sb_ + OFF_AH, (const char*)Ah + ao_, 8192, mbar_);        \
            bulk_cp(sb_ + OFF_AL, (const char*)Al + ao_, 8192, mbar_);        \
        }                                                                     \
    } while (0)

    // ---------- compute setup: 4x2 warp grid, 32x64 warp tile ----------
    const int warp_m = (wid & 3) * 32, warp_n = (wid >> 2) * 64;
    const uint32_t half = (uint32_t)(lane >> 4);
    uint32_t aRow[2], aSw[2], bRow[4], bSw[4];
#pragma unroll
    for (int mi = 0; mi < 2; mi++) {
        const uint32_t R = (uint32_t)(warp_m + mi * 16 + (lane & 15));
        aRow[mi] = R * 64;
        aSw[mi] = (R >> 1) & 3;
    }
#pragma unroll
    for (int g = 0; g < 4; g++) {
        const uint32_t R = (uint32_t)(warp_n + g * 16 + (lane & 15));
        bRow[g] = R * 64;
        bSw[g] = (R >> 1) & 3;
    }

    float acc[2][8][4];
#pragma unroll
    for (int mi = 0; mi < 2; mi++)
#pragma unroll
        for (int nj = 0; nj < 8; nj++)
#pragma unroll
            for (int q = 0; q < 4; q++) acc[mi][nj][q] = 0.0f;

    LOADS(0, 0);
    LOADS(1, 1);

    for (int k = 0; k < nk; k++) {
        const int st = k % NST;
        mbar_wait(mb[st], (k / NST) & 1);
        __syncthreads();   // compute(k-1) finished everywhere -> stage (k+2)%NST free
        if (k + 2 < nk) LOADS(k + 2, (k + 2) % NST);

        const uint32_t sb = sbase + (uint32_t)st * STAGE;
#pragma unroll
        for (int ks = 0; ks < 2; ks++) {
            uint32_t ah[2][4], al[2][4];
#pragma unroll
            for (int mi = 0; mi < 2; mi++) {
                const uint32_t ad = sb + aRow[mi]
                    + ((((uint32_t)(ks << 1) + half + aSw[mi]) & 3) << 4);
                ldmat4(ah[mi], ad + OFF_AH);
                ldmat4(al[mi], ad + OFF_AL);
            }
            // double-buffered B fragments: prefetch g+1 before g's HMMAs
            uint32_t bh[2][4], bl[2][4];
            {
                const uint32_t bd0 = sb + bRow[0]
                    + ((((uint32_t)(ks << 1) + half + bSw[0]) & 3) << 4);
                ldmat4(bh[0], bd0 + OFF_BH);
                ldmat4(bl[0], bd0 + OFF_BL);
            }
#pragma unroll
            for (int g = 0; g < 4; g++) {
                const int cur = g & 1, nxt = cur ^ 1;
                if (g < 3) {
                    const uint32_t bd = sb + bRow[g + 1]
                        + ((((uint32_t)(ks << 1) + half + bSw[g + 1]) & 3) << 4);
                    ldmat4(bh[nxt], bd + OFF_BH);
                    ldmat4(bl[nxt], bd + OFF_BL);
                }
#pragma unroll
                for (int mi = 0; mi < 2; mi++) {
                    mma16816(acc[mi][2 * g],     ah[mi], bh[cur][0], bh[cur][2]);
                    mma16816(acc[mi][2 * g + 1], ah[mi], bh[cur][1], bh[cur][3]);
                }
#pragma unroll
                for (int mi = 0; mi < 2; mi++) {
                    mma16816(acc[mi][2 * g],     al[mi], bh[cur][0], bh[cur][2]);
                    mma16816(acc[mi][2 * g + 1], al[mi], bh[cur][1], bh[cur][3]);
                }
#pragma unroll
                for (int mi = 0; mi < 2; mi++) {
                    mma16816(acc[mi][2 * g],     ah[mi], bl[cur][0], bl[cur][2]);
                    mma16816(acc[mi][2 * g + 1], ah[mi], bl[cur][1], bl[cur][3]);
                }
            }
        }
    }

    // ---------- epilogue ----------
    const int er = lane >> 2, ec = (lane & 3) * 2;
#pragma unroll
    for (int mi = 0; mi < 2; mi++) {
        const int rbase = m0 + warp_m + mi * 16 + er;
#pragma unroll
        for (int nj = 0; nj < 8; nj++) {
            const int col = n0 + warp_n + nj * 8 + ec;
            const float b0 = bias[col] * bscale, b1 = bias[col + 1] * bscale;
            float2 v;
            v.x = acc[mi][nj][0] + b0;
            v.y = acc[mi][nj][1] + b1;
            *(float2*)&C[(size_t)rbase * Ntot + col] = v;
            v.x = acc[mi][nj][2] + b0;
            v.y = acc[mi][nj][3] + b1;
            *(float2*)&C[(size_t)(rbase + 8) * Ntot + col] = v;
        }
    }
#undef LOADS
}

// -------------------- cell / epilogue kernels (2-wide) ----------------------
__device__ __forceinline__ float sigf(float x) { return 1.0f / (1.0f + expf(-x)); }

__device__ __forceinline__ size_t chunk_off(int row, int k, long plane) {
    const int kc = k >> 5;
    const uint32_t g = ((uint32_t)(k & 31)) >> 3;
    const size_t byte = (size_t)kc * plane + (size_t)row * 64
                      + swz(g, (uint32_t)row) + (size_t)(k & 7) * 2;
    return byte >> 1;   // bf16 index
}

__device__ __forceinline__ void split_store(float v, __nv_bfloat16* hi,
                                            __nv_bfloat16* lo, size_t half_idx) {
    const __nv_bfloat16 h = __float2bfloat16(v);
    hi[half_idx] = h;
    lo[half_idx] = __float2bfloat16(v - __bfloat162float(h));
}

// store a pair (n even): node-major + chunked plane (if planeNext > 0)
__device__ __forceinline__ void store_h2(size_t ob, float h0, float h1,
                                         int r, int n, long planeNext) {
    const __nv_bfloat16 hi0 = __float2bfloat16(h0);
    const __nv_bfloat16 hi1 = __float2bfloat16(h1);
    __nv_bfloat162 hh, ll;
    hh.x = hi0; hh.y = hi1;
    ll.x = __float2bfloat16(h0 - __bfloat162float(hi0));
    ll.y = __float2bfloat16(h1 - __bfloat162float(hi1));
    *(__nv_bfloat162*)&g_hh[ob] = hh;
    *(__nv_bfloat162*)&g_hl[ob] = ll;
    if (planeNext > 0) {
        const int R = r >> 1;
        const int k = (r & 1) * 512 + n;      // n even -> same granule for pair
        const size_t ci = chunk_off(R, k, planeNext);
        *(__nv_bfloat162*)&g_ahh[ci] = hh;
        *(__nv_bfloat162*)&g_ahl[ci] = ll;
    }
}

__global__ void cell_leaf_kernel(const float* __restrict__ buf)
{
    const int p = blockIdx.x * blockDim.x + threadIdx.x;
    if (p >= B_ * LVS * H_ / 2) return;
    const int n = (p & 255) << 1;
    const int r = p >> 8;
    const float* row = buf + (size_t)r * TH;
    const float2 iv = *(const float2*)(row + n);
    const float2 ov = *(const float2*)(row + n + 512);
    const float2 uv = *(const float2*)(row + n + 1024);
    const float cn0 = sigf(iv.x) * tanhf(uv.x);
    const float hn0 = sigf(ov.x) * tanhf(cn0);
    const float cn1 = sigf(iv.y) * tanhf(uv.y);
    const float hn1 = sigf(ov.y) * tanhf(cn1);
    const int b = r >> 8, leaf = r & 255;
    const size_t ob = ((size_t)b * NN + leaf) * H_ + n;
    float2 cv; cv.x = cn0; cv.y = cn1;
    *(float2*)&g_c[ob] = cv;
    store_h2(ob, hn0, hn1, r, n, (long)B_ * 128 * 64);   // level-1 A plane
}

// nsplit partial buffers at stride splitE; split 0 already contains bias.
__global__ void cell_level_kernel(const float* __restrict__ buf,
                                  int lm, int off, int off_prev, int total2,
                                  int nsplit, size_t splitE, long planeNext)
{
    const int p = blockIdx.x * blockDim.x + threadIdx.x;
    if (p >= total2) return;
    const int n = (p & 255) << 1;
    const int r = p >> 8;
    const int b = r >> lm;
    const int j = r & ((1 << lm) - 1);
    const size_t base = (size_t)r * NC;
    float2 iv = *(const float2*)(buf + base + n);
    float2 ov = *(const float2*)(buf + base + n + 512);
    float2 uv = *(const float2*)(buf + base + n + 1024);
    float2 f0 = *(const float2*)(buf + base + n + 1536);
    float2 f1 = *(const float2*)(buf + base + n + 2048);
    for (int s = 1; s < nsplit; s++) {
        const size_t sb = base + (size_t)s * splitE;
        const float2 a0 = *(const float2*)(buf + sb + n);
        const float2 a1 = *(const float2*)(buf + sb + n + 512);
        const float2 a2 = *(const float2*)(buf + sb + n + 1024);
        const float2 a3 = *(const float2*)(buf + sb + n + 1536);
        const float2 a4 = *(const float2*)(buf + sb + n + 2048);
        iv.x += a0.x; iv.y += a0.y;
        ov.x += a1.x; ov.y += a1.y;
        uv.x += a2.x; uv.y += a2.y;
        f0.x += a3.x; f0.y += a3.y;
        f1.x += a4.x; f1.y += a4.y;
    }
    const size_t cb = ((size_t)b * NN + off_prev + 2 * j) * H_ + n;
    const float2 cl = *(const float2*)&g_c[cb];
    const float2 cr = *(const float2*)&g_c[cb + H_];
    const float cf0 = sigf(f0.x) * cl.x + sigf(f1.x) * cr.x;
    const float cf1 = sigf(f0.y) * cl.y + sigf(f1.y) * cr.y;
    const float cn0 = sigf(iv.x) * tanhf(uv.x) + cf0;
    const float hn0 = sigf(ov.x) * tanhf(cn0);
    const float cn1 = sigf(iv.y) * tanhf(uv.y) + cf1;
    const float hn1 = sigf(ov.y) * tanhf(cn1);
    const size_t ob = ((size_t)b * NN + off + j) * H_ + n;
    float2 cv; cv.x = cn0; cv.y = cn1;
    *(float2*)&g_c[ob] = cv;
    store_h2(ob, hn0, hn1, r, n, planeNext);
}

// -------------------- classifier: one warp per node --------------------------
__global__ void classify_kernel(const float* __restrict__ lw,
                                const float* __restrict__ lb,
                                float* __restrict__ out)
{
    const int gw = (blockIdx.x * blockDim.x + threadIdx.x) >> 5;
    if (gw >= B_ * NN) return;
    const int lane = threadIdx.x & 31;
    const __nv_bfloat162* hh = (const __nv_bfloat162*)(g_hh + (size_t)gw * H_);
    const __nv_bfloat162* hl = (const __nv_bfloat162*)(g_hl + (size_t)gw * H_);
    float acc[5] = {0.f, 0.f, 0.f, 0.f, 0.f};
#pragma unroll
    for (int i = 0; i < 8; i++) {
        const int k2 = lane + 32 * i;                 // bf16x2 index 0..255
        const float2 a = __bfloat1622float2(hh[k2]);
        const float2 b = __bfloat1622float2(hl[k2]);
        const float h0 = a.x + b.x, h1 = a.y + b.y;
#pragma unroll
        for (int c = 0; c < 5; c++) {
            const float2 w = *(const float2*)(lw + (size_t)c * H_ + 2 * k2);
            acc[c] += h0 * w.x + h1 * w.y;
        }
    }
#pragma unroll
    for (int c = 0; c < 5; c++)
#pragma unroll
        for (int off = 16; off > 0; off >>= 1)
            acc[c] += __shfl_xor_sync(0xFFFFFFFF, acc[c], off);
    if (lane < 5)
        out[(size_t)gw * 5 + lane] = acc[lane] + lb[lane];
}

// -------------------- packing / gather (chunked + swizzled) -----------------
__global__ void pack_wcat_kernel(const float* __restrict__ Uiou,
                                 const float* __restrict__ Uf,
                                 const float* __restrict__ bi,
                                 const float* __restrict__ bf)
{
    const int idx = blockIdx.x * blockDim.x + threadIdx.x;
    if (idx >= NC * 1024) return;
    const int n = idx >> 10, k = idx & 1023;
    const float v = (n < TH) ? Uiou[(size_t)n * 1024 + k]
                             : Uf[(size_t)(n - TH) * 1024 + k];
    split_store(v, g_wch, g_wcl, chunk_off(n, k, PLANE_WC));
    if (k == 0) g_bc[n] = (n < TH) ? bi[n] : bf[n - TH];
}

__global__ void pack_wleaf_kernel(const float* __restrict__ W)
{
    const int idx = blockIdx.x * blockDim.x + threadIdx.x;
    if (idx >= TH * KLF) return;
    const int n = idx / KLF, k = idx - n * KLF;
    const float v = (k < X_) ? W[(size_t)n * X_ + k] : 0.0f;
    split_store(v, g_wlh, g_wll, chunk_off(n, k, PLANE_WL));
}

__global__ void gather_x_kernel(const int* __restrict__ wid,
                                const float* __restrict__ emb)
{
    const int r = blockIdx.x;
    const int c = threadIdx.x;
    if (c >= KLF) return;
    const float v = (c < X_) ? emb[(size_t)wid[r] * X_ + c] : 0.0f;
    split_store(v, g_xh, g_xl, chunk_off(r, c, PLANE_X));
}

// -------------------- launch ------------------------------------------------
extern "C" void kernel_launch(void* const* d_in, const int* in_sizes, int n_in,
                              void* d_out, int out_size)
{
    const int*   wordid  = (const int*)  d_in[0];
    const float* emb     = (const float*)d_in[1];
    const float* W_iou_w = (const float*)d_in[2];
    const float* W_iou_b = (const float*)d_in[3];
    const float* U_iou_w = (const float*)d_in[4];
    const float* U_iou_b = (const float*)d_in[5];
    const float* U_f_w   = (const float*)d_in[6];
    const float* U_f_b   = (const float*)d_in[7];
    const float* lin_w   = (const float*)d_in[8];
    const float* lin_b   = (const float*)d_in[9];
    float* out = (float*)d_out;
    (void)in_sizes; (void)n_in; (void)out_size;

    float *pbuf, *pbc;
    __nv_bfloat16 *pahh, *pahl, *pxh, *pxl, *pwch, *pwcl, *pwlh, *pwll;
    cudaGetSymbolAddress((void**)&pbuf, g_buf);
    cudaGetSymbolAddress((void**)&pbc,  g_bc);
    cudaGetSymbolAddress((void**)&pahh, g_ahh);
    cudaGetSymbolAddress((void**)&pahl, g_ahl);
    cudaGetSymbolAddress((void**)&pxh,  g_xh);
    cudaGetSymbolAddress((void**)&pxl,  g_xl);
    cudaGetSymbolAddress((void**)&pwch, g_wch);
    cudaGetSymbolAddress((void**)&pwcl, g_wcl);
    cudaGetSymbolAddress((void**)&pwlh, g_wlh);
    cudaGetSymbolAddress((void**)&pwll, g_wll);

    cudaFuncSetAttribute(gemm_mma_kernel,
                         cudaFuncAttributeMaxDynamicSharedMemorySize, SMEM_BYTES);

    // ---- prep ----
    pack_wcat_kernel <<<(NC * 1024 + 255) / 256, 256>>>(U_iou_w, U_f_w,
                                                        U_iou_b, U_f_b);
    pack_wleaf_kernel<<<(TH * KLF + 255) / 256, 256>>>(W_iou_w);
    gather_x_kernel  <<<B_ * LVS, KLF>>>(wordid, emb);

    // ---- leaves: all-bulk GEMM + cell (writes chunked h for level 1) ----
    {
        dim3 g(TH / BN, (B_ * LVS) / BM, 1);   // 12 x 512
        gemm_mma_kernel<<<g, 256, SMEM_BYTES>>>(
            pxh, pxl, pwlh, pwll, W_iou_b, pbuf,
            TH, PLANE_WL, PLANE_X, KLF / BK, 0);
        cell_leaf_kernel<<<(B_ * LVS * H_ / 2 + 255) / 256, 256>>>(pbuf);
    }

    // ---- internal levels: all-bulk GEMM; tuned split-K ---------------------
    static const int offs[10]   = {0, 256, 384, 448, 480, 496, 504, 508, 510, 511};
    static const int splits[9]  = {0, 1, 1, 1, 2, 4, 4, 8, 8};
    for (int l = 1; l <= 8; l++) {
        const int m = LVS >> l;
        const int M = B_ * m;
        const int lm = 8 - l;
        const int S = splits[l];
        const size_t splitE = (size_t)M * NC;
        const long planeA = (long)M * 64;              // this level's A plane
        const long planeNext = (l < 8) ? (long)(M / 2) * 64 : 0;
        dim3 g(NC / BN, M / BM, S);
        gemm_mma_kernel<<<g, 256, SMEM_BYTES>>>(
            pahh, pahl, pwch, pwcl, pbc, pbuf,
            NC, PLANE_WC, planeA, (1024 / BK) / S, splitE);
        const int total2 = M * H_ / 2;
        cell_level_kernel<<<(total2 + 255) / 256, 256>>>(pbuf, lm, offs[l],
                                                         offs[l - 1], total2,
                                                         S, splitE, planeNext);
    }

    // ---- classifier: one warp per node ----
    classify_kernel<<<(B_ * NN * 32 + 255) / 256, 256>>>(lin_w, lin_b, out);
}